// round 10
// baseline (speedup 1.0000x reference)
#include <cuda_runtime.h>
#include <math.h>

// Problem constants
#define NB 128      // batch
#define HD 512      // hidden
#define LS 512      // source length
#define TT 128      // target length (MAXLEN)
#define SS 64       // num symbols
#define G3 1536     // 3*H

// ---------------- scratch (device globals; no allocation allowed) ----------
__device__ float    g_enc_out[NB * LS * HD];   // [n][l][h]  134 MB
__device__ float    g_h[NB * HD];              // current hidden state
__device__ float    g_ghp[8 * NB * G3];        // split-K partials (8 slices)
__device__ float    g_embp[SS * G3];           // emb @ dec_Wih^T + dec_bih
__device__ float    g_Q[NB * TT * HD];         // decoder GRU outputs [n][t][h]
__device__ float    g_ctx[NB * TT * HD];       // attention context
__device__ float    g_ff[NB * TT * HD];        // attn_ff output
// Dataflow flags (monotonic step counters), 64-word (256B) stride each.
__device__ unsigned g_fa_e[128 * 64];   // enc: partials+staging done (idx jb*8+ks)
__device__ unsigned g_fb_e[128 * 64];   // enc: gate done            (idx ks*16+jb)
__device__ unsigned g_fa_d[128 * 64];   // dec: partials+staging done
__device__ unsigned g_fb_d[128 * 64];   // dec: gate done

__device__ __forceinline__ float sigf(float v) { return 1.f / (1.f + expf(-v)); }

// ---------------- init kernel ----------------------------------------------
__global__ void init_enc_kernel() {
    int i = blockIdx.x * 256 + threadIdx.x;
    if (i < NB * HD) g_h[i] = 0.f;
    if (i < 128 * 64) {
        g_fa_e[i] = 0u; g_fb_e[i] = 0u;
        g_fa_d[i] = 0u; g_fb_d[i] = 0u;
    }
}

// ---------------- emb_proj: (64,1536) = emb(64,512) @ dec_Wih^T + bih ------
__global__ __launch_bounds__(256) void embproj_kernel(
    const float* __restrict__ emb, const float* __restrict__ Wih,
    const float* __restrict__ bih)
{
    __shared__ float se[HD];
    int s = blockIdx.x;
    for (int k = threadIdx.x; k < HD; k += 256) se[k] = emb[s * HD + k];
    __syncthreads();
    const float4* s4 = (const float4*)se;
    for (int j = threadIdx.x; j < G3; j += 256) {
        float a = bih[j];
        const float4* w4 = (const float4*)(Wih + j * HD);
        for (int k = 0; k < HD / 4; ++k) {
            float4 wv = w4[k];
            float4 sv = s4[k];
            a = fmaf(sv.x, wv.x, a);
            a = fmaf(sv.y, wv.y, a);
            a = fmaf(sv.z, wv.z, a);
            a = fmaf(sv.w, wv.w, a);
        }
        g_embp[s * G3 + j] = a;
    }
}

// ============================================================================
// Recurrent kernels. 128 CTAs = ks(8 k-slices of 64) x jb(16 j-tiles of 32).
// GEMM identical to R9 (at FFMA floor). Synchronization is a point-to-point
// dataflow pipeline (no global barriers):
//   fa[jb*8+ks]  = t+1 : CTA finished GEMM t (staged h) + stored partials.
//   fb[ks*16+jb] = t+1 : CTA finished gate t (wrote its h block).
// Gate assignment: CTA (ks,jb) gates rows n in [jb*8,jb*8+8), cols
// j in [ks*64,ks*64+64)  (coalesced; 2 elems/thread).
// Gate wait  : fa of 8 partial producers (jb' in {2ks,2ks+1} x ks') AND
//              fa of 16 h-readers (group ks) [overwrite hazard].
// GEMM wait  : fb of 16 h-writers (group ks) AND fb of 16 partial readers
//              (group jb>>1) [overwrite hazard].
// ============================================================================

// ---------------- encoder persistent kernel --------------------------------
__global__ __launch_bounds__(256) void enc_kernel(
    const float* __restrict__ x, const float* __restrict__ Wih,
    const float* __restrict__ Whh, const float* __restrict__ bih,
    const float* __restrict__ bhh)
{
    __shared__ float sW[64][96];    // [k_local][g*32+jj]
    __shared__ float sH[32][128];   // [k_local][n]

    const int tid = threadIdx.x;
    const int bid = blockIdx.x;
    const int ks = bid & 7;              // k-slice 0..7 (64 wide)
    const int jb = bid >> 3;             // j tile 0..15 (32 cols)
    const int j0 = jb * 32, kb = ks * 64;
    const int tx = tid & 15, ty = tid >> 4;
    const int nl = ty * 8;               // 8 n rows per thread

    // Load weight slice ONCE, k-major.
#pragma unroll
    for (int it = 0; it < 6; ++it) {
        int idx = tid + it * 256;
        int jrow = idx % 96;
        int kc = (idx / 96) * 4;
        int g = jrow >> 5, jj = jrow & 31;
        float4 w = *(const float4*)(Whh + (g * HD + j0 + jj) * HD + kb + kc);
        sW[kc + 0][jrow] = w.x;
        sW[kc + 1][jrow] = w.y;
        sW[kc + 2][jrow] = w.z;
        sW[kc + 3][jrow] = w.w;
    }

    for (int t = 0; t < LS; ++t) {
        // ---- wait: h-writers of my k-slice + readers of my partial buffer ----
        if (t > 0) {
            unsigned pt = (unsigned)t;
            if (tid < 32) {
                int idx = (tid < 16) ? (ks * 16 + tid)
                                     : ((jb >> 1) * 16 + (tid - 16));
                volatile unsigned* p = &g_fb_e[idx * 64];
                while (*p < pt) { }
            }
            __syncthreads();
            __threadfence();
        }

        float acc[3][8][2];
#pragma unroll
        for (int g = 0; g < 3; g++)
#pragma unroll
            for (int i = 0; i < 8; i++) { acc[g][i][0] = 0.f; acc[g][i][1] = 0.f; }

#pragma unroll
        for (int st = 0; st < 2; ++st) {
            int k0 = kb + st * 32;
#pragma unroll
            for (int it = 0; it < 4; ++it) {
                int idx = tid + it * 256;
                int n = idx & 127;
                int kc = (idx >> 7) * 4;
                float4 h4 = __ldcg((const float4*)(g_h + n * HD + k0 + kc));
                sH[kc + 0][n] = h4.x;
                sH[kc + 1][n] = h4.y;
                sH[kc + 2][n] = h4.z;
                sH[kc + 3][n] = h4.w;
            }
            __syncthreads();

#pragma unroll 4
            for (int k = 0; k < 32; ++k) {
                float4 ha = *(const float4*)&sH[k][nl];
                float4 hb = *(const float4*)&sH[k][nl + 4];
                float2 w0 = *(const float2*)&sW[st * 32 + k][tx * 2];
                float2 w1 = *(const float2*)&sW[st * 32 + k][32 + tx * 2];
                float2 w2 = *(const float2*)&sW[st * 32 + k][64 + tx * 2];
                float hv[8] = {ha.x, ha.y, ha.z, ha.w, hb.x, hb.y, hb.z, hb.w};
#pragma unroll
                for (int i = 0; i < 8; i++) {
                    acc[0][i][0] = fmaf(hv[i], w0.x, acc[0][i][0]);
                    acc[0][i][1] = fmaf(hv[i], w0.y, acc[0][i][1]);
                    acc[1][i][0] = fmaf(hv[i], w1.x, acc[1][i][0]);
                    acc[1][i][1] = fmaf(hv[i], w1.y, acc[1][i][1]);
                    acc[2][i][0] = fmaf(hv[i], w2.x, acc[2][i][0]);
                    acc[2][i][1] = fmaf(hv[i], w2.y, acc[2][i][1]);
                }
            }
            __syncthreads();
        }

        // store partials (float2)
        const int jl = j0 + tx * 2;
#pragma unroll
        for (int g = 0; g < 3; g++)
#pragma unroll
            for (int i = 0; i < 8; i++)
                *(float2*)(g_ghp + (ks * NB + nl + i) * G3 + g * HD + jl) =
                    make_float2(acc[g][i][0], acc[g][i][1]);

        // ---- arrive A; wait for my gate's inputs + h-readers of my block ----
        unsigned tgt = (unsigned)(t + 1);
        __threadfence();
        __syncthreads();
        if (tid == 0) atomicExch(&g_fa_e[(jb * 8 + ks) * 64], tgt);
        if (tid < 32) {
            int idx;
            if (tid < 16) {
                int ksp = tid & 7;
                int jbp = 2 * ks + (tid >> 3);
                idx = jbp * 8 + ksp;               // partial producers
            } else {
                idx = (tid - 16) * 8 + ks;         // h-readers (group ks)
            }
            volatile unsigned* p = &g_fa_e[idx * 64];
            while (*p < tgt) { }
        }
        __syncthreads();
        __threadfence();

        // ---- gate: rows [jb*8, jb*8+8), cols [ks*64, ks*64+64) ----
#pragma unroll
        for (int e = 0; e < 2; ++e) {
            int elem = tid + e * 256;              // 0..511
            int n = jb * 8 + (elem >> 6);
            int j = ks * 64 + (elem & 63);
            float x0 = x[(n * 2 + 0) * LS + t];
            float x1 = x[(n * 2 + 1) * LS + t];
            float ghr = bhh[j], ghz = bhh[HD + j], ghn = bhh[2 * HD + j];
#pragma unroll
            for (int q = 0; q < 8; ++q) {
                const float* p = g_ghp + (q * NB + n) * G3 + j;
                ghr += __ldcg(p);
                ghz += __ldcg(p + HD);
                ghn += __ldcg(p + 2 * HD);
            }
            float gir = fmaf(x1, Wih[j * 2 + 1], fmaf(x0, Wih[j * 2], bih[j]));
            float giz = fmaf(x1, Wih[(HD + j) * 2 + 1],
                             fmaf(x0, Wih[(HD + j) * 2], bih[HD + j]));
            float gin = fmaf(x1, Wih[(2 * HD + j) * 2 + 1],
                             fmaf(x0, Wih[(2 * HD + j) * 2], bih[2 * HD + j]));
            float r = sigf(gir + ghr);
            float z = sigf(giz + ghz);
            float nn = tanhf(gin + r * ghn);
            float hold = __ldcg(g_h + n * HD + j);
            float hnew = (1.f - z) * nn + z * hold;
            g_h[n * HD + j] = hnew;
            g_enc_out[(n * LS + t) * HD + j] = hnew;
        }

        // ---- arrive B ----
        __threadfence();
        __syncthreads();
        if (tid == 0) atomicExch(&g_fb_e[(ks * 16 + jb) * 64], tgt);
    }
}

// ---------------- decoder persistent kernel --------------------------------
__global__ __launch_bounds__(256) void dec_kernel(
    const int* __restrict__ target, const float* __restrict__ Whh,
    const float* __restrict__ bhh)
{
    __shared__ float sW[64][96];
    __shared__ float sH[32][128];

    const int tid = threadIdx.x;
    const int bid = blockIdx.x;
    const int ks = bid & 7;
    const int jb = bid >> 3;
    const int j0 = jb * 32, kb = ks * 64;
    const int tx = tid & 15, ty = tid >> 4;
    const int nl = ty * 8;

#pragma unroll
    for (int it = 0; it < 6; ++it) {
        int idx = tid + it * 256;
        int jrow = idx % 96;
        int kc = (idx / 96) * 4;
        int g = jrow >> 5, jj = jrow & 31;
        float4 w = *(const float4*)(Whh + (g * HD + j0 + jj) * HD + kb + kc);
        sW[kc + 0][jrow] = w.x;
        sW[kc + 1][jrow] = w.y;
        sW[kc + 2][jrow] = w.z;
        sW[kc + 3][jrow] = w.w;
    }

    for (int t = 0; t < TT; ++t) {
        if (t > 0) {
            unsigned pt = (unsigned)t;
            if (tid < 32) {
                int idx = (tid < 16) ? (ks * 16 + tid)
                                     : ((jb >> 1) * 16 + (tid - 16));
                volatile unsigned* p = &g_fb_d[idx * 64];
                while (*p < pt) { }
            }
            __syncthreads();
            __threadfence();
        }

        float acc[3][8][2];
#pragma unroll
        for (int g = 0; g < 3; g++)
#pragma unroll
            for (int i = 0; i < 8; i++) { acc[g][i][0] = 0.f; acc[g][i][1] = 0.f; }

#pragma unroll
        for (int st = 0; st < 2; ++st) {
            int k0 = kb + st * 32;
#pragma unroll
            for (int it = 0; it < 4; ++it) {
                int idx = tid + it * 256;
                int n = idx & 127;
                int kc = (idx >> 7) * 4;
                float4 h4 = __ldcg((const float4*)(g_h + n * HD + k0 + kc));
                sH[kc + 0][n] = h4.x;
                sH[kc + 1][n] = h4.y;
                sH[kc + 2][n] = h4.z;
                sH[kc + 3][n] = h4.w;
            }
            __syncthreads();

#pragma unroll 4
            for (int k = 0; k < 32; ++k) {
                float4 ha = *(const float4*)&sH[k][nl];
                float4 hb = *(const float4*)&sH[k][nl + 4];
                float2 w0 = *(const float2*)&sW[st * 32 + k][tx * 2];
                float2 w1 = *(const float2*)&sW[st * 32 + k][32 + tx * 2];
                float2 w2 = *(const float2*)&sW[st * 32 + k][64 + tx * 2];
                float hv[8] = {ha.x, ha.y, ha.z, ha.w, hb.x, hb.y, hb.z, hb.w};
#pragma unroll
                for (int i = 0; i < 8; i++) {
                    acc[0][i][0] = fmaf(hv[i], w0.x, acc[0][i][0]);
                    acc[0][i][1] = fmaf(hv[i], w0.y, acc[0][i][1]);
                    acc[1][i][0] = fmaf(hv[i], w1.x, acc[1][i][0]);
                    acc[1][i][1] = fmaf(hv[i], w1.y, acc[1][i][1]);
                    acc[2][i][0] = fmaf(hv[i], w2.x, acc[2][i][0]);
                    acc[2][i][1] = fmaf(hv[i], w2.y, acc[2][i][1]);
                }
            }
            __syncthreads();
        }

        const int jl = j0 + tx * 2;
#pragma unroll
        for (int g = 0; g < 3; g++)
#pragma unroll
            for (int i = 0; i < 8; i++)
                *(float2*)(g_ghp + (ks * NB + nl + i) * G3 + g * HD + jl) =
                    make_float2(acc[g][i][0], acc[g][i][1]);

        unsigned tgt = (unsigned)(t + 1);
        __threadfence();
        __syncthreads();
        if (tid == 0) atomicExch(&g_fa_d[(jb * 8 + ks) * 64], tgt);
        if (tid < 32) {
            int idx;
            if (tid < 16) {
                int ksp = tid & 7;
                int jbp = 2 * ks + (tid >> 3);
                idx = jbp * 8 + ksp;
            } else {
                idx = (tid - 16) * 8 + ks;
            }
            volatile unsigned* p = &g_fa_d[idx * 64];
            while (*p < tgt) { }
        }
        __syncthreads();
        __threadfence();

#pragma unroll
        for (int e = 0; e < 2; ++e) {
            int elem = tid + e * 256;
            int n = jb * 8 + (elem >> 6);
            int j = ks * 64 + (elem & 63);
            int tok = (t == 0) ? 0 : target[n * TT + t - 1];
            const float* ep = g_embp + tok * G3;
            float gir = ep[j], giz = ep[HD + j], gin = ep[2 * HD + j];
            float ghr = bhh[j], ghz = bhh[HD + j], ghn = bhh[2 * HD + j];
#pragma unroll
            for (int q = 0; q < 8; ++q) {
                const float* p = g_ghp + (q * NB + n) * G3 + j;
                ghr += __ldcg(p);
                ghz += __ldcg(p + HD);
                ghn += __ldcg(p + 2 * HD);
            }
            float r = sigf(gir + ghr);
            float z = sigf(giz + ghz);
            float nn = tanhf(gin + r * ghn);
            float hold = __ldcg(g_h + n * HD + j);
            float hnew = (1.f - z) * nn + z * hold;
            g_h[n * HD + j] = hnew;
            g_Q[(n * TT + t) * HD + j] = hnew;
        }

        __threadfence();
        __syncthreads();
        if (tid == 0) atomicExch(&g_fb_d[(ks * 16 + jb) * 64], tgt);
    }
}

// ---------------- dec_hN copy ----------------------------------------------
__global__ void copyh_kernel(float* __restrict__ dst) {
    int i = blockIdx.x * 256 + threadIdx.x;
    dst[i] = g_h[i];
}

// ---------------- scores: S[n][i][l] = sum_h Q[n][i][h]*E[n][l][h] ---------
__global__ __launch_bounds__(256) void scores_kernel(float* __restrict__ outw)
{
    __shared__ float sq[64][36], se[64][36];
    int bid = blockIdx.x;
    int n = bid >> 4;
    int rr = bid & 15;
    int i0 = (rr >> 3) * 64, l0 = (rr & 7) * 64;
    int tid = threadIdx.x, tx = tid & 15, ty = tid >> 4;
    float acc[4][4];
#pragma unroll
    for (int i = 0; i < 4; i++)
#pragma unroll
        for (int l = 0; l < 4; l++) acc[i][l] = 0.f;

    for (int st = 0; st < 16; ++st) {
        int k0 = st * 32;
        for (int v = tid; v < 512; v += 256) {
            int r = v >> 3, c = (v & 7) * 4;
            *(float4*)&sq[r][c] =
                *(const float4*)(g_Q + (n * TT + i0 + r) * HD + k0 + c);
            *(float4*)&se[r][c] =
                *(const float4*)(g_enc_out + (n * LS + l0 + r) * HD + k0 + c);
        }
        __syncthreads();
#pragma unroll
        for (int k = 0; k < 32; ++k) {
            float qv[4], ev[4];
#pragma unroll
            for (int i = 0; i < 4; i++) qv[i] = sq[ty * 4 + i][k];
#pragma unroll
            for (int l = 0; l < 4; l++) ev[l] = se[tx * 4 + l][k];
#pragma unroll
            for (int i = 0; i < 4; i++)
#pragma unroll
                for (int l = 0; l < 4; l++)
                    acc[i][l] = fmaf(qv[i], ev[l], acc[i][l]);
        }
        __syncthreads();
    }
#pragma unroll
    for (int i = 0; i < 4; i++)
#pragma unroll
        for (int l = 0; l < 4; l++)
            outw[(size_t)(n * TT + i0 + ty * 4 + i) * LS + l0 + tx * 4 + l] = acc[i][l];
}

// ---------------- softmax over l (in-place in all_w region) ----------------
__global__ void softmax_kernel(float* __restrict__ w)
{
    int row = blockIdx.x * 8 + (threadIdx.x >> 5);
    int lane = threadIdx.x & 31;
    float* p = w + (size_t)row * LS;
    float v[16];
    float m = -1e30f;
#pragma unroll
    for (int u = 0; u < 16; ++u) { v[u] = p[lane + u * 32]; m = fmaxf(m, v[u]); }
#pragma unroll
    for (int o = 16; o; o >>= 1) m = fmaxf(m, __shfl_xor_sync(0xffffffffu, m, o));
    float s = 0.f;
#pragma unroll
    for (int u = 0; u < 16; ++u) { v[u] = expf(v[u] - m); s += v[u]; }
#pragma unroll
    for (int o = 16; o; o >>= 1) s += __shfl_xor_sync(0xffffffffu, s, o);
    float inv = 1.f / s;
#pragma unroll
    for (int u = 0; u < 16; ++u) p[lane + u * 32] = v[u] * inv;
}

// ---------------- context: C[n][i][h] = sum_l w[n][i][l]*E[n][l][h] --------
__global__ __launch_bounds__(256) void ctx_kernel(const float* __restrict__ w)
{
    __shared__ float swt[64][36];   // [i][l-chunk]
    __shared__ float se[32][68];    // [l-chunk][h]
    int bid = blockIdx.x;
    int n = bid >> 4;
    int rr = bid & 15;
    int i0 = (rr >> 3) * 64, h0 = (rr & 7) * 64;
    int tid = threadIdx.x, tx = tid & 15, ty = tid >> 4;
    float acc[4][4];
#pragma unroll
    for (int i = 0; i < 4; i++)
#pragma unroll
        for (int h = 0; h < 4; h++) acc[i][h] = 0.f;

    for (int st = 0; st < 16; ++st) {
        int l0 = st * 32;
        for (int v = tid; v < 512; v += 256) {
            int r = v >> 3, c = (v & 7) * 4;
            *(float4*)&swt[r][c] =
                *(const float4*)(w + (size_t)(n * TT + i0 + r) * LS + l0 + c);
        }
        for (int v = tid; v < 512; v += 256) {
            int r = v >> 4, c = (v & 15) * 4;
            *(float4*)&se[r][c] =
                *(const float4*)(g_enc_out + (n * LS + l0 + r) * HD + h0 + c);
        }
        __syncthreads();
#pragma unroll
        for (int k = 0; k < 32; ++k) {
            float wv[4], ev[4];
#pragma unroll
            for (int i = 0; i < 4; i++) wv[i] = swt[ty * 4 + i][k];
#pragma unroll
            for (int h = 0; h < 4; h++) ev[h] = se[k][tx * 4 + h];
#pragma unroll
            for (int i = 0; i < 4; i++)
#pragma unroll
                for (int h = 0; h < 4; h++)
                    acc[i][h] = fmaf(wv[i], ev[h], acc[i][h]);
        }
        __syncthreads();
    }
#pragma unroll
    for (int i = 0; i < 4; i++)
#pragma unroll
        for (int h = 0; h < 4; h++)
            g_ctx[(n * TT + i0 + ty * 4 + i) * HD + h0 + tx * 4 + h] = acc[i][h];
}

// ---------------- ff: g_ff[m][o] = [Q|ctx][m][:] . attn_ff_W[o][:] + b[o] --
__global__ __launch_bounds__(256) void ff_kernel(
    const float* __restrict__ W, const float* __restrict__ b)
{
    __shared__ float sa[64][36], swt[64][36];
    int bid = blockIdx.x;
    int m0 = (bid >> 3) * 64, o0 = (bid & 7) * 64;
    int tid = threadIdx.x, tx = tid & 15, ty = tid >> 4;
    float acc[4][4];
#pragma unroll
    for (int i = 0; i < 4; i++)
#pragma unroll
        for (int o = 0; o < 4; o++) acc[i][o] = 0.f;

    for (int st = 0; st < 32; ++st) {
        int k0 = st * 32;
        const float* A = (k0 < HD) ? g_Q : g_ctx;
        int koff = (k0 < HD) ? k0 : k0 - HD;
        for (int v = tid; v < 512; v += 256) {
            int r = v >> 3, c = (v & 7) * 4;
            *(float4*)&sa[r][c] = *(const float4*)(A + (m0 + r) * HD + koff + c);
            *(float4*)&swt[r][c] = *(const float4*)(W + (o0 + r) * (2 * HD) + k0 + c);
        }
        __syncthreads();
#pragma unroll
        for (int k = 0; k < 32; ++k) {
            float av[4], wv[4];
#pragma unroll
            for (int i = 0; i < 4; i++) av[i] = sa[ty * 4 + i][k];
#pragma unroll
            for (int o = 0; o < 4; o++) wv[o] = swt[tx * 4 + o][k];
#pragma unroll
            for (int i = 0; i < 4; i++)
#pragma unroll
                for (int o = 0; o < 4; o++)
                    acc[i][o] = fmaf(av[i], wv[o], acc[i][o]);
        }
        __syncthreads();
    }
#pragma unroll
    for (int i = 0; i < 4; i++)
#pragma unroll
        for (int o = 0; o < 4; o++)
            g_ff[(m0 + ty * 4 + i) * HD + o0 + tx * 4 + o] = acc[i][o] + b[o0 + tx * 4 + o];
}

// ---------------- fc: v_out[m][s] = ff[m][:] . fc_W[s][:] + fc_b[s] --------
__global__ __launch_bounds__(256) void fc_kernel(
    const float* __restrict__ W, const float* __restrict__ b,
    float* __restrict__ vout)
{
    __shared__ float sa[128][36], swt[64][36];
    int m0 = blockIdx.x * 128;
    int tid = threadIdx.x, tx = tid & 15, ty = tid >> 4;
    float acc[8][4];
#pragma unroll
    for (int i = 0; i < 8; i++)
#pragma unroll
        for (int s = 0; s < 4; s++) acc[i][s] = 0.f;

    for (int st = 0; st < 16; ++st) {
        int k0 = st * 32;
        for (int v = tid; v < 1024; v += 256) {
            int r = v >> 3, c = (v & 7) * 4;
            *(float4*)&sa[r][c] = *(const float4*)(g_ff + (m0 + r) * HD + k0 + c);
        }
        for (int v = tid; v < 512; v += 256) {
            int r = v >> 3, c = (v & 7) * 4;
            *(float4*)&swt[r][c] = *(const float4*)(W + r * HD + k0 + c);
        }
        __syncthreads();
#pragma unroll
        for (int k = 0; k < 32; ++k) {
            float av[8], wv[4];
#pragma unroll
            for (int i = 0; i < 8; i++) av[i] = sa[ty * 8 + i][k];
#pragma unroll
            for (int s = 0; s < 4; s++) wv[s] = swt[tx * 4 + s][k];
#pragma unroll
            for (int i = 0; i < 8; i++)
#pragma unroll
                for (int s = 0; s < 4; s++)
                    acc[i][s] = fmaf(av[i], wv[s], acc[i][s]);
        }
        __syncthreads();
    }
#pragma unroll
    for (int i = 0; i < 8; i++)
#pragma unroll
        for (int s = 0; s < 4; s++)
            vout[(m0 + ty * 8 + i) * SS + tx * 4 + s] = acc[i][s] + b[tx * 4 + s];
}

// ---------------- launch ----------------------------------------------------
extern "C" void kernel_launch(void* const* d_in, const int* in_sizes, int n_in,
                              void* d_out, int out_size)
{
    const float* x      = (const float*)d_in[0];
    const int*   target = (const int*)  d_in[1];
    const float* eWih   = (const float*)d_in[2];
    const float* eWhh   = (const float*)d_in[3];
    const float* ebih   = (const float*)d_in[4];
    const float* ebhh   = (const float*)d_in[5];
    const float* dWih   = (const float*)d_in[6];
    const float* dWhh   = (const float*)d_in[7];
    const float* dbih   = (const float*)d_in[8];
    const float* dbhh   = (const float*)d_in[9];
    const float* emb    = (const float*)d_in[10];
    const float* aW     = (const float*)d_in[11];
    const float* ab     = (const float*)d_in[12];
    const float* fW     = (const float*)d_in[13];
    const float* fb     = (const float*)d_in[14];

    float* out   = (float*)d_out;
    float* v_out = out;                       // (128,128,64)  = 1048576
    float* hN    = out + 1048576;             // (1,128,512)   = 65536
    float* allw  = out + 1048576 + 65536;     // (128,128,512) = 8388608

    init_enc_kernel<<<256, 256>>>();
    embproj_kernel<<<64, 256>>>(emb, dWih, dbih);
    enc_kernel<<<128, 256>>>(x, eWih, eWhh, ebih, ebhh);
    dec_kernel<<<128, 256>>>(target, dWhh, dbhh);
    copyh_kernel<<<256, 256>>>(hN);
    scores_kernel<<<2048, 256>>>(allw);
    softmax_kernel<<<2048, 256>>>(allw);
    ctx_kernel<<<2048, 256>>>(allw);
    ff_kernel<<<2048, 256>>>(aW, ab);
    fc_kernel<<<128, 256>>>(fW, fb, v_out);
}

// round 12
// speedup vs baseline: 1.2723x; 1.2723x over previous
#include <cuda_runtime.h>
#include <cuda_bf16.h>
#include <math.h>
#include <stdint.h>

// Problem constants
#define NB 128      // batch
#define HD 512      // hidden
#define LS 512      // source length
#define TT 128      // target length (MAXLEN)
#define SS 64       // num symbols
#define G3 1536     // 3*H

// ---------------- scratch (device globals; no allocation allowed) ----------
__device__ float          g_enc_out[NB * LS * HD];
__device__ float          g_h[NB * HD];
__device__ __nv_bfloat16  g_h_hi[NB * HD];
__device__ __nv_bfloat16  g_h_lo[NB * HD];
__device__ float          g_ghp[8 * NB * G3];   // split-K partials (8 slices)
__device__ float          g_embp[SS * G3];
__device__ float          g_Q[NB * TT * HD];
__device__ float          g_ctx[NB * TT * HD];
__device__ float          g_ff[NB * TT * HD];
__device__ unsigned       g_barc[1024];         // spread barrier counters

__device__ __forceinline__ float sigf(float v) { return 1.f / (1.f + expf(-v)); }

// Spread grid barrier (R9, proven): 8 counters, 16 arrivals each.
__device__ __forceinline__ void gsync(unsigned* ctr, unsigned target) {
    __threadfence();
    __syncthreads();
    if (threadIdx.x == 0)
        atomicAdd(ctr + (blockIdx.x & 7) * 64, 1u);
    if (threadIdx.x < 8) {
        volatile unsigned* p = ctr + threadIdx.x * 64;
        while (*p < target) { }
    }
    __syncthreads();
    __threadfence();
}

// bf16 warp MMA m16n8k16, row.col, f32 accum (sm_80+ baseline PTX).
__device__ __forceinline__ void mma16816(float* d,
                                         uint32_t a0, uint32_t a1,
                                         uint32_t a2, uint32_t a3,
                                         uint32_t b0, uint32_t b1) {
    asm volatile(
        "mma.sync.aligned.m16n8k16.row.col.f32.bf16.bf16.f32 "
        "{%0,%1,%2,%3}, {%4,%5,%6,%7}, {%8,%9}, {%0,%1,%2,%3};"
        : "+f"(d[0]), "+f"(d[1]), "+f"(d[2]), "+f"(d[3])
        : "r"(a0), "r"(a1), "r"(a2), "r"(a3), "r"(b0), "r"(b1));
}

// ---------------- init kernel ----------------------------------------------
__global__ void init_enc_kernel() {
    int i = blockIdx.x * 256 + threadIdx.x;
    if (i < NB * HD) {
        g_h[i] = 0.f;
        g_h_hi[i] = __float2bfloat16(0.f);
        g_h_lo[i] = __float2bfloat16(0.f);
    }
    if (i < 1024) g_barc[i] = 0u;
}

// ---------------- emb_proj --------------------------------------------------
__global__ __launch_bounds__(256) void embproj_kernel(
    const float* __restrict__ emb, const float* __restrict__ Wih,
    const float* __restrict__ bih)
{
    __shared__ float se[HD];
    int s = blockIdx.x;
    for (int k = threadIdx.x; k < HD; k += 256) se[k] = emb[s * HD + k];
    __syncthreads();
    const float4* s4 = (const float4*)se;
    for (int j = threadIdx.x; j < G3; j += 256) {
        float a = bih[j];
        const float4* w4 = (const float4*)(Wih + j * HD);
        for (int k = 0; k < HD / 4; ++k) {
            float4 wv = w4[k];
            float4 sv = s4[k];
            a = fmaf(sv.x, wv.x, a);
            a = fmaf(sv.y, wv.y, a);
            a = fmaf(sv.z, wv.z, a);
            a = fmaf(sv.w, wv.w, a);
        }
        g_embp[s * G3 + j] = a;
    }
}

// ============================================================================
// Recurrent kernels. 128 CTAs = ks(8 k-slices of 64) x jb(16 j-tiles of 32).
// CTA: partial gh for 128 n x 96 jrows (3g x 32j) x 64 k, via bf16 HMMA with
// hi/lo split. Weights resident in smem (hi/lo, stride 72); h staged per 32-k
// chunk (hi/lo, stride 40). Warp tiling: 2 m-tiles(16) x 6 n-tiles(8).
// Gate phase + spread barrier identical to R9 (best kernel).
// ============================================================================

#define SW_STR 72
#define SH_STR 40

// stage one 32-k chunk of bf16 h (hi or lo) into smem [128][32] stride 40
__device__ __forceinline__ void stage_h(__nv_bfloat16* dst,
                                        const __nv_bfloat16* __restrict__ src,
                                        int k0, int tid) {
    int n = tid >> 1, half = tid & 1;
    const uint4* s = (const uint4*)(src + n * HD + k0 + half * 16);
    uint4 v0 = __ldcg(s);
    uint4 v1 = __ldcg(s + 1);
    char* d = (char*)dst + n * (SH_STR * 2) + half * 32;
    *(uint4*)d = v0;
    *(uint4*)(d + 16) = v1;
}

// The shared recurrent GEMM body. Computes partials into g_ghp, then the
// caller does the gate. acc layout: [mt][j][4].
#define RNN_GEMM_BODY(HSRC_HI, HSRC_LO)                                        \
    float acc[2][6][4];                                                        \
    _Pragma("unroll")                                                          \
    for (int mt = 0; mt < 2; ++mt)                                             \
        _Pragma("unroll")                                                      \
        for (int j = 0; j < 6; ++j)                                            \
            _Pragma("unroll")                                                  \
            for (int u = 0; u < 4; ++u) acc[mt][j][u] = 0.f;                   \
    _Pragma("unroll")                                                          \
    for (int c = 0; c < 2; ++c) {                                              \
        int k0 = kb + c * 32;                                                  \
        stage_h(sHh, HSRC_HI, k0, tid);                                        \
        stage_h(sHl, HSRC_LO, k0, tid);                                        \
        __syncthreads();                                                       \
        _Pragma("unroll")                                                      \
        for (int kk = 0; kk < 2; ++kk) {                                       \
            int kl = kk * 16 + q2;                                             \
            uint32_t ah[2][4], al[2][4];                                       \
            _Pragma("unroll")                                                  \
            for (int mt = 0; mt < 2; ++mt) {                                   \
                int r0 = (wid & 3) * 32 + mt * 16 + gid;                       \
                ah[mt][0] = *(const uint32_t*)&sHh[r0 * SH_STR + kl];          \
                ah[mt][1] = *(const uint32_t*)&sHh[(r0 + 8) * SH_STR + kl];    \
                ah[mt][2] = *(const uint32_t*)&sHh[r0 * SH_STR + kl + 8];      \
                ah[mt][3] = *(const uint32_t*)&sHh[(r0 + 8) * SH_STR + kl + 8];\
                al[mt][0] = *(const uint32_t*)&sHl[r0 * SH_STR + kl];          \
                al[mt][1] = *(const uint32_t*)&sHl[(r0 + 8) * SH_STR + kl];    \
                al[mt][2] = *(const uint32_t*)&sHl[r0 * SH_STR + kl + 8];      \
                al[mt][3] = *(const uint32_t*)&sHl[(r0 + 8) * SH_STR + kl + 8];\
            }                                                                  \
            int kg = c * 32 + kk * 16 + q2;                                    \
            _Pragma("unroll")                                                  \
            for (int j = 0; j < 6; ++j) {                                      \
                int jr = ((wid >> 2) * 6 + j) * 8 + gid;                       \
                uint32_t bh0 = *(const uint32_t*)&sWh[jr * SW_STR + kg];       \
                uint32_t bh1 = *(const uint32_t*)&sWh[jr * SW_STR + kg + 8];   \
                uint32_t bl0 = *(const uint32_t*)&sWl[jr * SW_STR + kg];       \
                uint32_t bl1 = *(const uint32_t*)&sWl[jr * SW_STR + kg + 8];   \
                _Pragma("unroll")                                              \
                for (int mt = 0; mt < 2; ++mt) {                               \
                    mma16816(acc[mt][j], ah[mt][0], ah[mt][1], ah[mt][2],      \
                             ah[mt][3], bh0, bh1);                             \
                    mma16816(acc[mt][j], ah[mt][0], ah[mt][1], ah[mt][2],      \
                             ah[mt][3], bl0, bl1);                             \
                    mma16816(acc[mt][j], al[mt][0], al[mt][1], al[mt][2],      \
                             al[mt][3], bh0, bh1);                             \
                }                                                              \
            }                                                                  \
        }                                                                      \
        __syncthreads();                                                       \
    }                                                                          \
    _Pragma("unroll")                                                          \
    for (int mt = 0; mt < 2; ++mt)                                             \
        _Pragma("unroll")                                                      \
        for (int j = 0; j < 6; ++j) {                                          \
            int jr = ((wid >> 2) * 6 + j) * 8 + q2;                            \
            int g = jr >> 5, jj = jr & 31;                                     \
            int n = (wid & 3) * 32 + mt * 16 + gid;                            \
            float* bp = g_ghp + (size_t)(ks * NB + n) * G3 + g * HD + j0 + jj; \
            *(float2*)bp = make_float2(acc[mt][j][0], acc[mt][j][1]);          \
            *(float2*)(bp + 8 * G3) =                                          \
                make_float2(acc[mt][j][2], acc[mt][j][3]);                     \
        }

// weight conversion: fp32 Whh CTA slice -> hi/lo bf16 smem
#define RNN_LOAD_W(WSRC)                                                       \
    _Pragma("unroll")                                                          \
    for (int it = 0; it < 24; ++it) {                                          \
        int idx = tid + it * 256;                                              \
        int r = idx >> 6, k = idx & 63;                                        \
        int g = r >> 5, jj = r & 31;                                           \
        float w = WSRC[(g * HD + j0 + jj) * HD + kb + k];                      \
        __nv_bfloat16 hi = __float2bfloat16(w);                                \
        __nv_bfloat16 lo = __float2bfloat16(w - __bfloat162float(hi));         \
        sWh[r * SW_STR + k] = hi;                                              \
        sWl[r * SW_STR + k] = lo;                                              \
    }

// ---------------- encoder persistent kernel --------------------------------
__global__ __launch_bounds__(256) void enc_kernel(
    const float* __restrict__ x, const float* __restrict__ Wih,
    const float* __restrict__ Whh, const float* __restrict__ bih,
    const float* __restrict__ bhh)
{
    __shared__ __nv_bfloat16 sWh[96 * SW_STR];
    __shared__ __nv_bfloat16 sWl[96 * SW_STR];
    __shared__ __nv_bfloat16 sHh[128 * SH_STR];
    __shared__ __nv_bfloat16 sHl[128 * SH_STR];

    const int tid = threadIdx.x;
    const int bid = blockIdx.x;
    const int wid = tid >> 5;
    const int lane = tid & 31;
    const int gid = lane >> 2;
    const int q2 = (lane & 3) * 2;
    const int ks = bid & 7;
    const int jb = bid >> 3;
    const int j0 = jb * 32, kb = ks * 64;

    RNN_LOAD_W(Whh)
    __syncthreads();

    unsigned bt = 0;
    for (int t = 0; t < LS; ++t) {
        RNN_GEMM_BODY(g_h_hi, g_h_lo)
        bt += 16; gsync(g_barc, bt);

        // gate phase: 65536 (n,j) over 32768 threads
        int Gt = bid * 256 + tid;
#pragma unroll
        for (int e = 0; e < 2; ++e) {
            int idx = Gt + e * 32768;
            int n = idx >> 9, j = idx & 511;
            float x0 = x[(n * 2 + 0) * LS + t];
            float x1 = x[(n * 2 + 1) * LS + t];
            float ghr = bhh[j], ghz = bhh[HD + j], ghn = bhh[2 * HD + j];
#pragma unroll
            for (int q = 0; q < 8; ++q) {
                const float* p = g_ghp + (size_t)(q * NB + n) * G3 + j;
                ghr += __ldcg(p);
                ghz += __ldcg(p + HD);
                ghn += __ldcg(p + 2 * HD);
            }
            float gir = fmaf(x1, Wih[j * 2 + 1], fmaf(x0, Wih[j * 2], bih[j]));
            float giz = fmaf(x1, Wih[(HD + j) * 2 + 1],
                             fmaf(x0, Wih[(HD + j) * 2], bih[HD + j]));
            float gin = fmaf(x1, Wih[(2 * HD + j) * 2 + 1],
                             fmaf(x0, Wih[(2 * HD + j) * 2], bih[2 * HD + j]));
            float r = sigf(gir + ghr);
            float z = sigf(giz + ghz);
            float nn = tanhf(gin + r * ghn);
            float hold = __ldcg(g_h + n * HD + j);
            float hnew = (1.f - z) * nn + z * hold;
            g_h[n * HD + j] = hnew;
            __nv_bfloat16 hh = __float2bfloat16(hnew);
            g_h_hi[n * HD + j] = hh;
            g_h_lo[n * HD + j] = __float2bfloat16(hnew - __bfloat162float(hh));
            g_enc_out[(size_t)(n * LS + t) * HD + j] = hnew;
        }
        bt += 16; gsync(g_barc, bt);
    }
}

// ---------------- decoder persistent kernel --------------------------------
__global__ __launch_bounds__(256) void dec_kernel(
    const int* __restrict__ target, const float* __restrict__ Whh,
    const float* __restrict__ bhh)
{
    __shared__ __nv_bfloat16 sWh[96 * SW_STR];
    __shared__ __nv_bfloat16 sWl[96 * SW_STR];
    __shared__ __nv_bfloat16 sHh[128 * SH_STR];
    __shared__ __nv_bfloat16 sHl[128 * SH_STR];

    const int tid = threadIdx.x;
    const int bid = blockIdx.x;
    const int wid = tid >> 5;
    const int lane = tid & 31;
    const int gid = lane >> 2;
    const int q2 = (lane & 3) * 2;
    const int ks = bid & 7;
    const int jb = bid >> 3;
    const int j0 = jb * 32, kb = ks * 64;

    RNN_LOAD_W(Whh)
    __syncthreads();

    unsigned bt = 0;
    for (int t = 0; t < TT; ++t) {
        RNN_GEMM_BODY(g_h_hi, g_h_lo)
        bt += 16; gsync(g_barc + 512, bt);

        int Gt = bid * 256 + tid;
#pragma unroll
        for (int e = 0; e < 2; ++e) {
            int idx = Gt + e * 32768;
            int n = idx >> 9, j = idx & 511;
            int tok = (t == 0) ? 0 : target[n * TT + t - 1];
            const float* ep = g_embp + tok * G3;
            float gir = ep[j], giz = ep[HD + j], gin = ep[2 * HD + j];
            float ghr = bhh[j], ghz = bhh[HD + j], ghn = bhh[2 * HD + j];
#pragma unroll
            for (int q = 0; q < 8; ++q) {
                const float* p = g_ghp + (size_t)(q * NB + n) * G3 + j;
                ghr += __ldcg(p);
                ghz += __ldcg(p + HD);
                ghn += __ldcg(p + 2 * HD);
            }
            float r = sigf(gir + ghr);
            float z = sigf(giz + ghz);
            float nn = tanhf(gin + r * ghn);
            float hold = __ldcg(g_h + n * HD + j);
            float hnew = (1.f - z) * nn + z * hold;
            g_h[n * HD + j] = hnew;
            __nv_bfloat16 hh = __float2bfloat16(hnew);
            g_h_hi[n * HD + j] = hh;
            g_h_lo[n * HD + j] = __float2bfloat16(hnew - __bfloat162float(hh));
            g_Q[(size_t)(n * TT + t) * HD + j] = hnew;
        }
        bt += 16; gsync(g_barc + 512, bt);
    }
}

// ---------------- dec_hN copy ----------------------------------------------
__global__ void copyh_kernel(float* __restrict__ dst) {
    int i = blockIdx.x * 256 + threadIdx.x;
    dst[i] = g_h[i];
}

// ---------------- scores: S[n][i][l] = sum_h Q[n][i][h]*E[n][l][h] ---------
__global__ __launch_bounds__(256) void scores_kernel(float* __restrict__ outw)
{
    __shared__ float sq[64][36], se[64][36];
    int bid = blockIdx.x;
    int n = bid >> 4;
    int rr = bid & 15;
    int i0 = (rr >> 3) * 64, l0 = (rr & 7) * 64;
    int tid = threadIdx.x, tx = tid & 15, ty = tid >> 4;
    float acc[4][4];
#pragma unroll
    for (int i = 0; i < 4; i++)
#pragma unroll
        for (int l = 0; l < 4; l++) acc[i][l] = 0.f;

    for (int st = 0; st < 16; ++st) {
        int k0 = st * 32;
        for (int v = tid; v < 512; v += 256) {
            int r = v >> 3, c = (v & 7) * 4;
            *(float4*)&sq[r][c] =
                *(const float4*)(g_Q + (size_t)(n * TT + i0 + r) * HD + k0 + c);
            *(float4*)&se[r][c] =
                *(const float4*)(g_enc_out + (size_t)(n * LS + l0 + r) * HD + k0 + c);
        }
        __syncthreads();
#pragma unroll
        for (int k = 0; k < 32; ++k) {
            float qv[4], ev[4];
#pragma unroll
            for (int i = 0; i < 4; i++) qv[i] = sq[ty * 4 + i][k];
#pragma unroll
            for (int l = 0; l < 4; l++) ev[l] = se[tx * 4 + l][k];
#pragma unroll
            for (int i = 0; i < 4; i++)
#pragma unroll
                for (int l = 0; l < 4; l++)
                    acc[i][l] = fmaf(qv[i], ev[l], acc[i][l]);
        }
        __syncthreads();
    }
#pragma unroll
    for (int i = 0; i < 4; i++)
#pragma unroll
        for (int l = 0; l < 4; l++)
            outw[(size_t)(n * TT + i0 + ty * 4 + i) * LS + l0 + tx * 4 + l] = acc[i][l];
}

// ---------------- softmax over l (in-place) ---------------------------------
__global__ void softmax_kernel(float* __restrict__ w)
{
    int row = blockIdx.x * 8 + (threadIdx.x >> 5);
    int lane = threadIdx.x & 31;
    float* p = w + (size_t)row * LS;
    float v[16];
    float m = -1e30f;
#pragma unroll
    for (int u = 0; u < 16; ++u) { v[u] = p[lane + u * 32]; m = fmaxf(m, v[u]); }
#pragma unroll
    for (int o = 16; o; o >>= 1) m = fmaxf(m, __shfl_xor_sync(0xffffffffu, m, o));
    float s = 0.f;
#pragma unroll
    for (int u = 0; u < 16; ++u) { v[u] = expf(v[u] - m); s += v[u]; }
#pragma unroll
    for (int o = 16; o; o >>= 1) s += __shfl_xor_sync(0xffffffffu, s, o);
    float inv = 1.f / s;
#pragma unroll
    for (int u = 0; u < 16; ++u) p[lane + u * 32] = v[u] * inv;
}

// ---------------- context: C[n][i][h] = sum_l w[n][i][l]*E[n][l][h] --------
__global__ __launch_bounds__(256) void ctx_kernel(const float* __restrict__ w)
{
    __shared__ float swt[64][36];
    __shared__ float se[32][68];
    int bid = blockIdx.x;
    int n = bid >> 4;
    int rr = bid & 15;
    int i0 = (rr >> 3) * 64, h0 = (rr & 7) * 64;
    int tid = threadIdx.x, tx = tid & 15, ty = tid >> 4;
    float acc[4][4];
#pragma unroll
    for (int i = 0; i < 4; i++)
#pragma unroll
        for (int h = 0; h < 4; h++) acc[i][h] = 0.f;

    for (int st = 0; st < 16; ++st) {
        int l0 = st * 32;
        for (int v = tid; v < 512; v += 256) {
            int r = v >> 3, c = (v & 7) * 4;
            *(float4*)&swt[r][c] =
                *(const float4*)(w + (size_t)(n * TT + i0 + r) * LS + l0 + c);
        }
        for (int v = tid; v < 512; v += 256) {
            int r = v >> 4, c = (v & 15) * 4;
            *(float4*)&se[r][c] =
                *(const float4*)(g_enc_out + (size_t)(n * LS + l0 + r) * HD + h0 + c);
        }
        __syncthreads();
#pragma unroll
        for (int k = 0; k < 32; ++k) {
            float wv[4], ev[4];
#pragma unroll
            for (int i = 0; i < 4; i++) wv[i] = swt[ty * 4 + i][k];
#pragma unroll
            for (int h = 0; h < 4; h++) ev[h] = se[k][tx * 4 + h];
#pragma unroll
            for (int i = 0; i < 4; i++)
#pragma unroll
                for (int h = 0; h < 4; h++)
                    acc[i][h] = fmaf(wv[i], ev[h], acc[i][h]);
        }
        __syncthreads();
    }
#pragma unroll
    for (int i = 0; i < 4; i++)
#pragma unroll
        for (int h = 0; h < 4; h++)
            g_ctx[(size_t)(n * TT + i0 + ty * 4 + i) * HD + h0 + tx * 4 + h] = acc[i][h];
}

// ---------------- ff ---------------------------------------------------------
__global__ __launch_bounds__(256) void ff_kernel(
    const float* __restrict__ W, const float* __restrict__ b)
{
    __shared__ float sa[64][36], swt[64][36];
    int bid = blockIdx.x;
    int m0 = (bid >> 3) * 64, o0 = (bid & 7) * 64;
    int tid = threadIdx.x, tx = tid & 15, ty = tid >> 4;
    float acc[4][4];
#pragma unroll
    for (int i = 0; i < 4; i++)
#pragma unroll
        for (int o = 0; o < 4; o++) acc[i][o] = 0.f;

    for (int st = 0; st < 32; ++st) {
        int k0 = st * 32;
        const float* A = (k0 < HD) ? g_Q : g_ctx;
        int koff = (k0 < HD) ? k0 : k0 - HD;
        for (int v = tid; v < 512; v += 256) {
            int r = v >> 3, c = (v & 7) * 4;
            *(float4*)&sa[r][c] = *(const float4*)(A + (size_t)(m0 + r) * HD + koff + c);
            *(float4*)&swt[r][c] = *(const float4*)(W + (size_t)(o0 + r) * (2 * HD) + k0 + c);
        }
        __syncthreads();
#pragma unroll
        for (int k = 0; k < 32; ++k) {
            float av[4], wv[4];
#pragma unroll
            for (int i = 0; i < 4; i++) av[i] = sa[ty * 4 + i][k];
#pragma unroll
            for (int o = 0; o < 4; o++) wv[o] = swt[tx * 4 + o][k];
#pragma unroll
            for (int i = 0; i < 4; i++)
#pragma unroll
                for (int o = 0; o < 4; o++)
                    acc[i][o] = fmaf(av[i], wv[o], acc[i][o]);
        }
        __syncthreads();
    }
#pragma unroll
    for (int i = 0; i < 4; i++)
#pragma unroll
        for (int o = 0; o < 4; o++)
            g_ff[(size_t)(m0 + ty * 4 + i) * HD + o0 + tx * 4 + o] = acc[i][o] + b[o0 + tx * 4 + o];
}

// ---------------- fc ---------------------------------------------------------
__global__ __launch_bounds__(256) void fc_kernel(
    const float* __restrict__ W, const float* __restrict__ b,
    float* __restrict__ vout)
{
    __shared__ float sa[128][36], swt[64][36];
    int m0 = blockIdx.x * 128;
    int tid = threadIdx.x, tx = tid & 15, ty = tid >> 4;
    float acc[8][4];
#pragma unroll
    for (int i = 0; i < 8; i++)
#pragma unroll
        for (int s = 0; s < 4; s++) acc[i][s] = 0.f;

    for (int st = 0; st < 16; ++st) {
        int k0 = st * 32;
        for (int v = tid; v < 1024; v += 256) {
            int r = v >> 3, c = (v & 7) * 4;
            *(float4*)&sa[r][c] = *(const float4*)(g_ff + (size_t)(m0 + r) * HD + k0 + c);
        }
        for (int v = tid; v < 512; v += 256) {
            int r = v >> 3, c = (v & 7) * 4;
            *(float4*)&swt[r][c] = *(const float4*)(W + (size_t)r * HD + k0 + c);
        }
        __syncthreads();
#pragma unroll
        for (int k = 0; k < 32; ++k) {
            float av[8], wv[4];
#pragma unroll
            for (int i = 0; i < 8; i++) av[i] = sa[ty * 8 + i][k];
#pragma unroll
            for (int s = 0; s < 4; s++) wv[s] = swt[tx * 4 + s][k];
#pragma unroll
            for (int i = 0; i < 8; i++)
#pragma unroll
                for (int s = 0; s < 4; s++)
                    acc[i][s] = fmaf(av[i], wv[s], acc[i][s]);
        }
        __syncthreads();
    }
#pragma unroll
    for (int i = 0; i < 8; i++)
#pragma unroll
        for (int s = 0; s < 4; s++)
            vout[(size_t)(m0 + ty * 8 + i) * SS + tx * 4 + s] = acc[i][s] + b[tx * 4 + s];
}

// ---------------- launch ----------------------------------------------------
extern "C" void kernel_launch(void* const* d_in, const int* in_sizes, int n_in,
                              void* d_out, int out_size)
{
    const float* x      = (const float*)d_in[0];
    const int*   target = (const int*)  d_in[1];
    const float* eWih   = (const float*)d_in[2];
    const float* eWhh   = (const float*)d_in[3];
    const float* ebih   = (const float*)d_in[4];
    const float* ebhh   = (const float*)d_in[5];
    const float* dWih   = (const float*)d_in[6];
    const float* dWhh   = (const float*)d_in[7];
    const float* dbih   = (const float*)d_in[8];
    const float* dbhh   = (const float*)d_in[9];
    const float* emb    = (const float*)d_in[10];
    const float* aW     = (const float*)d_in[11];
    const float* ab     = (const float*)d_in[12];
    const float* fW     = (const float*)d_in[13];
    const float* fb     = (const float*)d_in[14];

    float* out   = (float*)d_out;
    float* v_out = out;                       // (128,128,64)
    float* hN    = out + 1048576;             // (1,128,512)
    float* allw  = out + 1048576 + 65536;     // (128,128,512)

    init_enc_kernel<<<256, 256>>>();
    embproj_kernel<<<64, 256>>>(emb, dWih, dbih);
    enc_kernel<<<128, 256>>>(x, eWih, eWhh, ebih, ebhh);
    dec_kernel<<<128, 256>>>(target, dWhh, dbhh);
    copyh_kernel<<<256, 256>>>(hN);
    scores_kernel<<<2048, 256>>>(allw);
    softmax_kernel<<<2048, 256>>>(allw);
    ctx_kernel<<<2048, 256>>>(allw);
    ff_kernel<<<2048, 256>>>(aW, ab);
    fc_kernel<<<128, 256>>>(fW, fb, v_out);
}

// round 13
// speedup vs baseline: 1.2741x; 1.0014x over previous
#include <cuda_runtime.h>
#include <cuda_bf16.h>
#include <math.h>
#include <stdint.h>

// Problem constants
#define NB 128      // batch
#define HD 512      // hidden
#define LS 512      // source length
#define TT 128      // target length (MAXLEN)
#define SS 64       // num symbols
#define G3 1536     // 3*H

// ---------------- scratch (device globals; no allocation allowed) ----------
__device__ float          g_enc_out[NB * LS * HD];
__device__ __nv_bfloat16  g_eo_hi[NB * LS * HD];
__device__ __nv_bfloat16  g_eo_lo[NB * LS * HD];
__device__ float          g_h[NB * HD];
__device__ __nv_bfloat16  g_h_hi[NB * HD];
__device__ __nv_bfloat16  g_h_lo[NB * HD];
__device__ float          g_ghp[4 * NB * G3];   // split-K partials (4 slices)
__device__ float          g_embp[SS * G3];
__device__ float          g_Q[NB * TT * HD];
__device__ __nv_bfloat16  g_q_hi[NB * TT * HD];
__device__ __nv_bfloat16  g_q_lo[NB * TT * HD];
__device__ float          g_ctx[NB * TT * HD];
__device__ float          g_ff[NB * TT * HD];
__device__ unsigned       g_barc[1024];         // spread barrier counters

__device__ __forceinline__ float sigf(float v) { return 1.f / (1.f + expf(-v)); }

// Spread grid barrier (proven): 8 counters, 16 arrivals each.
__device__ __forceinline__ void gsync(unsigned* ctr, unsigned target) {
    __threadfence();
    __syncthreads();
    if (threadIdx.x == 0)
        atomicAdd(ctr + (blockIdx.x & 7) * 64, 1u);
    if (threadIdx.x < 8) {
        volatile unsigned* p = ctr + threadIdx.x * 64;
        while (*p < target) { }
    }
    __syncthreads();
    __threadfence();
}

// bf16 warp MMA m16n8k16, row.col, f32 accum (sm_80+ baseline PTX).
__device__ __forceinline__ void mma16816(float* d,
                                         uint32_t a0, uint32_t a1,
                                         uint32_t a2, uint32_t a3,
                                         uint32_t b0, uint32_t b1) {
    asm volatile(
        "mma.sync.aligned.m16n8k16.row.col.f32.bf16.bf16.f32 "
        "{%0,%1,%2,%3}, {%4,%5,%6,%7}, {%8,%9}, {%0,%1,%2,%3};"
        : "+f"(d[0]), "+f"(d[1]), "+f"(d[2]), "+f"(d[3])
        : "r"(a0), "r"(a1), "r"(a2), "r"(a3), "r"(b0), "r"(b1));
}

// ---------------- init kernel ----------------------------------------------
__global__ void init_enc_kernel() {
    int i = blockIdx.x * 256 + threadIdx.x;
    if (i < NB * HD) {
        g_h[i] = 0.f;
        g_h_hi[i] = __float2bfloat16(0.f);
        g_h_lo[i] = __float2bfloat16(0.f);
    }
    if (i < 1024) g_barc[i] = 0u;
}

// ---------------- emb_proj --------------------------------------------------
__global__ __launch_bounds__(256) void embproj_kernel(
    const float* __restrict__ emb, const float* __restrict__ Wih,
    const float* __restrict__ bih)
{
    __shared__ float se[HD];
    int s = blockIdx.x;
    for (int k = threadIdx.x; k < HD; k += 256) se[k] = emb[s * HD + k];
    __syncthreads();
    const float4* s4 = (const float4*)se;
    for (int j = threadIdx.x; j < G3; j += 256) {
        float a = bih[j];
        const float4* w4 = (const float4*)(Wih + j * HD);
        for (int k = 0; k < HD / 4; ++k) {
            float4 wv = w4[k];
            float4 sv = s4[k];
            a = fmaf(sv.x, wv.x, a);
            a = fmaf(sv.y, wv.y, a);
            a = fmaf(sv.z, wv.z, a);
            a = fmaf(sv.w, wv.w, a);
        }
        g_embp[s * G3 + j] = a;
    }
}

// ============================================================================
// Recurrent kernels. 128 CTAs = ksl(4 k-slices of 128) x jb(32 j-tiles of 16).
// CTA: partial gh for 128 n x 48 jrows (3g x 16j) x 128 k, via bf16 HMMA
// hi/lo. Weights resident (hi/lo, stride 136). h staged per 32-k chunk
// (hi/lo, stride 40) with REGISTER PREFETCH double-buffering.
// Warp tiling: mw=wid&3 (2 m-tiles of 16), nw=wid>>2 (3 n-tiles of 8).
// ============================================================================

#define SW_STR 136
#define SH_STR 40

// stage one 32-k chunk of bf16 h (hi or lo) into smem [128][32] stride 40
__device__ __forceinline__ void stage_h(__nv_bfloat16* dst,
                                        const __nv_bfloat16* __restrict__ src,
                                        int k0, int tid) {
    int n = tid >> 1, half = tid & 1;
    const uint4* s = (const uint4*)(src + n * HD + k0 + half * 16);
    uint4 v0 = __ldcg(s);
    uint4 v1 = __ldcg(s + 1);
    char* d = (char*)dst + n * (SH_STR * 2) + half * 32;
    *(uint4*)d = v0;
    *(uint4*)(d + 16) = v1;
}

// Shared recurrent GEMM body: partials into g_ghp. acc[mt][nt][4].
#define RNN_GEMM_BODY()                                                        \
    float acc[2][3][4];                                                        \
    _Pragma("unroll")                                                          \
    for (int mt = 0; mt < 2; ++mt)                                             \
        _Pragma("unroll")                                                      \
        for (int j = 0; j < 3; ++j)                                            \
            _Pragma("unroll")                                                  \
            for (int u = 0; u < 4; ++u) acc[mt][j][u] = 0.f;                   \
    stage_h(sHh, g_h_hi, kb, tid);                                             \
    stage_h(sHl, g_h_lo, kb, tid);                                             \
    __syncthreads();                                                           \
    _Pragma("unroll")                                                          \
    for (int c = 0; c < 4; ++c) {                                              \
        uint4 ph0, ph1, pl0, pl1;                                              \
        if (c < 3) {                                                           \
            int n_ = tid >> 1, half = tid & 1;                                 \
            const uint4* sh_ = (const uint4*)(g_h_hi + n_ * HD + kb +          \
                                              (c + 1) * 32 + half * 16);       \
            const uint4* sl_ = (const uint4*)(g_h_lo + n_ * HD + kb +          \
                                              (c + 1) * 32 + half * 16);       \
            ph0 = __ldcg(sh_); ph1 = __ldcg(sh_ + 1);                          \
            pl0 = __ldcg(sl_); pl1 = __ldcg(sl_ + 1);                          \
        }                                                                      \
        _Pragma("unroll")                                                      \
        for (int kk = 0; kk < 2; ++kk) {                                       \
            int kl = kk * 16 + q2;                                             \
            uint32_t ah[2][4], al[2][4];                                       \
            _Pragma("unroll")                                                  \
            for (int mt = 0; mt < 2; ++mt) {                                   \
                int r0 = mw * 32 + mt * 16 + gid;                              \
                ah[mt][0] = *(const uint32_t*)&sHh[r0 * SH_STR + kl];          \
                ah[mt][1] = *(const uint32_t*)&sHh[(r0 + 8) * SH_STR + kl];    \
                ah[mt][2] = *(const uint32_t*)&sHh[r0 * SH_STR + kl + 8];      \
                ah[mt][3] = *(const uint32_t*)&sHh[(r0 + 8) * SH_STR + kl + 8];\
                al[mt][0] = *(const uint32_t*)&sHl[r0 * SH_STR + kl];          \
                al[mt][1] = *(const uint32_t*)&sHl[(r0 + 8) * SH_STR + kl];    \
                al[mt][2] = *(const uint32_t*)&sHl[r0 * SH_STR + kl + 8];      \
                al[mt][3] = *(const uint32_t*)&sHl[(r0 + 8) * SH_STR + kl + 8];\
            }                                                                  \
            int kg = c * 32 + kk * 16 + q2;                                    \
            _Pragma("unroll")                                                  \
            for (int j = 0; j < 3; ++j) {                                      \
                int jr = nw * 24 + j * 8 + gid;                                \
                uint32_t bh0 = *(const uint32_t*)&sWh[jr * SW_STR + kg];       \
                uint32_t bh1 = *(const uint32_t*)&sWh[jr * SW_STR + kg + 8];   \
                uint32_t bl0 = *(const uint32_t*)&sWl[jr * SW_STR + kg];       \
                uint32_t bl1 = *(const uint32_t*)&sWl[jr * SW_STR + kg + 8];   \
                _Pragma("unroll")                                              \
                for (int mt = 0; mt < 2; ++mt) {                               \
                    mma16816(acc[mt][j], ah[mt][0], ah[mt][1], ah[mt][2],      \
                             ah[mt][3], bh0, bh1);                             \
                    mma16816(acc[mt][j], ah[mt][0], ah[mt][1], ah[mt][2],      \
                             ah[mt][3], bl0, bl1);                             \
                    mma16816(acc[mt][j], al[mt][0], al[mt][1], al[mt][2],      \
                             al[mt][3], bh0, bh1);                             \
                }                                                              \
            }                                                                  \
        }                                                                      \
        __syncthreads();                                                       \
        if (c < 3) {                                                           \
            int n_ = tid >> 1, half = tid & 1;                                 \
            char* dh = (char*)sHh + n_ * (SH_STR * 2) + half * 32;             \
            *(uint4*)dh = ph0; *(uint4*)(dh + 16) = ph1;                       \
            char* dl = (char*)sHl + n_ * (SH_STR * 2) + half * 32;             \
            *(uint4*)dl = pl0; *(uint4*)(dl + 16) = pl1;                       \
            __syncthreads();                                                   \
        }                                                                      \
    }                                                                          \
    _Pragma("unroll")                                                          \
    for (int mt = 0; mt < 2; ++mt)                                             \
        _Pragma("unroll")                                                      \
        for (int j = 0; j < 3; ++j) {                                          \
            int jr = nw * 24 + j * 8 + q2;                                     \
            int g = jr >> 4, jj = jr & 15;                                     \
            int n = mw * 32 + mt * 16 + gid;                                   \
            float* bp = g_ghp + (size_t)(ksl * NB + n) * G3 + g * HD + j0 + jj;\
            *(float2*)bp = make_float2(acc[mt][j][0], acc[mt][j][1]);          \
            *(float2*)(bp + 8 * G3) =                                          \
                make_float2(acc[mt][j][2], acc[mt][j][3]);                     \
        }

// weight conversion: fp32 Whh CTA slice -> hi/lo bf16 smem (48 jr x 128 k)
#define RNN_LOAD_W(WSRC)                                                       \
    _Pragma("unroll")                                                          \
    for (int it = 0; it < 24; ++it) {                                          \
        int idx = tid + it * 256;                                              \
        int r = idx >> 7, k = idx & 127;                                       \
        int g = r >> 4, jj = r & 15;                                           \
        float w = WSRC[(g * HD + j0 + jj) * HD + kb + k];                      \
        __nv_bfloat16 hi = __float2bfloat16(w);                                \
        __nv_bfloat16 lo = __float2bfloat16(w - __bfloat162float(hi));         \
        sWh[r * SW_STR + k] = hi;                                              \
        sWl[r * SW_STR + k] = lo;                                              \
    }

// ---------------- encoder persistent kernel --------------------------------
__global__ __launch_bounds__(256) void enc_kernel(
    const float* __restrict__ x, const float* __restrict__ Wih,
    const float* __restrict__ Whh, const float* __restrict__ bih,
    const float* __restrict__ bhh)
{
    __shared__ __nv_bfloat16 sWh[48 * SW_STR];
    __shared__ __nv_bfloat16 sWl[48 * SW_STR];
    __shared__ __nv_bfloat16 sHh[128 * SH_STR];
    __shared__ __nv_bfloat16 sHl[128 * SH_STR];

    const int tid = threadIdx.x;
    const int bid = blockIdx.x;
    const int wid = tid >> 5;
    const int lane = tid & 31;
    const int gid = lane >> 2;
    const int q2 = (lane & 3) * 2;
    const int mw = wid & 3;
    const int nw = wid >> 2;
    const int ksl = bid & 3;
    const int jb = bid >> 2;
    const int j0 = jb * 16, kb = ksl * 128;

    RNN_LOAD_W(Whh)
    __syncthreads();

    unsigned bt = 0;
    for (int t = 0; t < LS; ++t) {
        RNN_GEMM_BODY()
        bt += 16; gsync(g_barc, bt);

        // gate phase: 65536 (n,j) over 32768 threads
        int Gt = bid * 256 + tid;
#pragma unroll
        for (int e = 0; e < 2; ++e) {
            int idx = Gt + e * 32768;
            int n = idx >> 9, j = idx & 511;
            float x0 = x[(n * 2 + 0) * LS + t];
            float x1 = x[(n * 2 + 1) * LS + t];
            float ghr = bhh[j], ghz = bhh[HD + j], ghn = bhh[2 * HD + j];
#pragma unroll
            for (int q = 0; q < 4; ++q) {
                const float* p = g_ghp + (size_t)(q * NB + n) * G3 + j;
                ghr += __ldcg(p);
                ghz += __ldcg(p + HD);
                ghn += __ldcg(p + 2 * HD);
            }
            float gir = fmaf(x1, Wih[j * 2 + 1], fmaf(x0, Wih[j * 2], bih[j]));
            float giz = fmaf(x1, Wih[(HD + j) * 2 + 1],
                             fmaf(x0, Wih[(HD + j) * 2], bih[HD + j]));
            float gin = fmaf(x1, Wih[(2 * HD + j) * 2 + 1],
                             fmaf(x0, Wih[(2 * HD + j) * 2], bih[2 * HD + j]));
            float r = sigf(gir + ghr);
            float z = sigf(giz + ghz);
            float nn = tanhf(gin + r * ghn);
            float hold = __ldcg(g_h + n * HD + j);
            float hnew = (1.f - z) * nn + z * hold;
            g_h[n * HD + j] = hnew;
            __nv_bfloat16 hh = __float2bfloat16(hnew);
            __nv_bfloat16 hl = __float2bfloat16(hnew - __bfloat162float(hh));
            g_h_hi[n * HD + j] = hh;
            g_h_lo[n * HD + j] = hl;
            size_t eo = (size_t)(n * LS + t) * HD + j;
            g_enc_out[eo] = hnew;
            g_eo_hi[eo] = hh;
            g_eo_lo[eo] = hl;
        }
        bt += 16; gsync(g_barc, bt);
    }
}

// ---------------- decoder persistent kernel --------------------------------
__global__ __launch_bounds__(256) void dec_kernel(
    const int* __restrict__ target, const float* __restrict__ Whh,
    const float* __restrict__ bhh)
{
    __shared__ __nv_bfloat16 sWh[48 * SW_STR];
    __shared__ __nv_bfloat16 sWl[48 * SW_STR];
    __shared__ __nv_bfloat16 sHh[128 * SH_STR];
    __shared__ __nv_bfloat16 sHl[128 * SH_STR];

    const int tid = threadIdx.x;
    const int bid = blockIdx.x;
    const int wid = tid >> 5;
    const int lane = tid & 31;
    const int gid = lane >> 2;
    const int q2 = (lane & 3) * 2;
    const int mw = wid & 3;
    const int nw = wid >> 2;
    const int ksl = bid & 3;
    const int jb = bid >> 2;
    const int j0 = jb * 16, kb = ksl * 128;

    RNN_LOAD_W(Whh)
    __syncthreads();

    unsigned bt = 0;
    for (int t = 0; t < TT; ++t) {
        RNN_GEMM_BODY()
        bt += 16; gsync(g_barc + 512, bt);

        int Gt = bid * 256 + tid;
#pragma unroll
        for (int e = 0; e < 2; ++e) {
            int idx = Gt + e * 32768;
            int n = idx >> 9, j = idx & 511;
            int tok = (t == 0) ? 0 : target[n * TT + t - 1];
            const float* ep = g_embp + tok * G3;
            float gir = ep[j], giz = ep[HD + j], gin = ep[2 * HD + j];
            float ghr = bhh[j], ghz = bhh[HD + j], ghn = bhh[2 * HD + j];
#pragma unroll
            for (int q = 0; q < 4; ++q) {
                const float* p = g_ghp + (size_t)(q * NB + n) * G3 + j;
                ghr += __ldcg(p);
                ghz += __ldcg(p + HD);
                ghn += __ldcg(p + 2 * HD);
            }
            float r = sigf(gir + ghr);
            float z = sigf(giz + ghz);
            float nn = tanhf(gin + r * ghn);
            float hold = __ldcg(g_h + n * HD + j);
            float hnew = (1.f - z) * nn + z * hold;
            g_h[n * HD + j] = hnew;
            __nv_bfloat16 hh = __float2bfloat16(hnew);
            __nv_bfloat16 hl = __float2bfloat16(hnew - __bfloat162float(hh));
            g_h_hi[n * HD + j] = hh;
            g_h_lo[n * HD + j] = hl;
            size_t qo = (size_t)(n * TT + t) * HD + j;
            g_Q[qo] = hnew;
            g_q_hi[qo] = hh;
            g_q_lo[qo] = hl;
        }
        bt += 16; gsync(g_barc + 512, bt);
    }
}

// ---------------- dec_hN copy ----------------------------------------------
__global__ void copyh_kernel(float* __restrict__ dst) {
    int i = blockIdx.x * 256 + threadIdx.x;
    dst[i] = g_h[i];
}

// ---------------- scores via HMMA: S[n][i][l] = sum_h Q·E -------------------
// grid 1024 = n(128) x l-tile(8 of 64). CTA tile M=128(i) x N=64(l), K=512.
__global__ __launch_bounds__(256) void scores_kernel(float* __restrict__ outw)
{
    __shared__ __nv_bfloat16 sAh[128 * SH_STR];
    __shared__ __nv_bfloat16 sAl[128 * SH_STR];
    __shared__ __nv_bfloat16 sBh[64 * SH_STR];
    __shared__ __nv_bfloat16 sBl[64 * SH_STR];

    const int tid = threadIdx.x;
    const int bid = blockIdx.x;
    const int n = bid >> 3;
    const int l0 = (bid & 7) * 64;
    const int wid = tid >> 5;
    const int lane = tid & 31;
    const int gid = lane >> 2;
    const int q2 = (lane & 3) * 2;
    const int mw = wid & 3;
    const int nw = wid >> 2;

    const __nv_bfloat16* Ah = g_q_hi + (size_t)n * TT * HD;
    const __nv_bfloat16* Al = g_q_lo + (size_t)n * TT * HD;
    const __nv_bfloat16* Bh = g_eo_hi + (size_t)(n * LS + l0) * HD;
    const __nv_bfloat16* Bl = g_eo_lo + (size_t)(n * LS + l0) * HD;

    float acc[2][4][4];
#pragma unroll
    for (int mt = 0; mt < 2; ++mt)
#pragma unroll
        for (int nt = 0; nt < 4; ++nt)
#pragma unroll
            for (int u = 0; u < 4; ++u) acc[mt][nt][u] = 0.f;

    for (int c = 0; c < 16; ++c) {
        int k0 = c * 32;
        stage_h(sAh, Ah, k0, tid);
        stage_h(sAl, Al, k0, tid);
        {
            int r = tid >> 2, q8 = (tid & 3) * 8;
            uint4 vh = __ldcg((const uint4*)(Bh + (size_t)r * HD + k0 + q8));
            uint4 vl = __ldcg((const uint4*)(Bl + (size_t)r * HD + k0 + q8));
            *(uint4*)((char*)sBh + r * (SH_STR * 2) + q8 * 2) = vh;
            *(uint4*)((char*)sBl + r * (SH_STR * 2) + q8 * 2) = vl;
        }
        __syncthreads();
#pragma unroll
        for (int kk = 0; kk < 2; ++kk) {
            int kl = kk * 16 + q2;
            uint32_t ah[2][4], al[2][4];
#pragma unroll
            for (int mt = 0; mt < 2; ++mt) {
                int r0 = mw * 32 + mt * 16 + gid;
                ah[mt][0] = *(const uint32_t*)&sAh[r0 * SH_STR + kl];
                ah[mt][1] = *(const uint32_t*)&sAh[(r0 + 8) * SH_STR + kl];
                ah[mt][2] = *(const uint32_t*)&sAh[r0 * SH_STR + kl + 8];
                ah[mt][3] = *(const uint32_t*)&sAh[(r0 + 8) * SH_STR + kl + 8];
                al[mt][0] = *(const uint32_t*)&sAl[r0 * SH_STR + kl];
                al[mt][1] = *(const uint32_t*)&sAl[(r0 + 8) * SH_STR + kl];
                al[mt][2] = *(const uint32_t*)&sAl[r0 * SH_STR + kl + 8];
                al[mt][3] = *(const uint32_t*)&sAl[(r0 + 8) * SH_STR + kl + 8];
            }
#pragma unroll
            for (int nt = 0; nt < 4; ++nt) {
                int lr = nw * 32 + nt * 8 + gid;
                uint32_t bh0 = *(const uint32_t*)&sBh[lr * SH_STR + kl];
                uint32_t bh1 = *(const uint32_t*)&sBh[lr * SH_STR + kl + 8];
                uint32_t bl0 = *(const uint32_t*)&sBl[lr * SH_STR + kl];
                uint32_t bl1 = *(const uint32_t*)&sBl[lr * SH_STR + kl + 8];
#pragma unroll
                for (int mt = 0; mt < 2; ++mt) {
                    mma16816(acc[mt][nt], ah[mt][0], ah[mt][1], ah[mt][2],
                             ah[mt][3], bh0, bh1);
                    mma16816(acc[mt][nt], ah[mt][0], ah[mt][1], ah[mt][2],
                             ah[mt][3], bl0, bl1);
                    mma16816(acc[mt][nt], al[mt][0], al[mt][1], al[mt][2],
                             al[mt][3], bh0, bh1);
                }
            }
        }
        __syncthreads();
    }
#pragma unroll
    for (int mt = 0; mt < 2; ++mt)
#pragma unroll
        for (int nt = 0; nt < 4; ++nt) {
            int i = mw * 32 + mt * 16 + gid;
            int l = l0 + nw * 32 + nt * 8 + q2;
            float* op = outw + (size_t)(n * TT + i) * LS + l;
            *(float2*)op = make_float2(acc[mt][nt][0], acc[mt][nt][1]);
            *(float2*)(op + (size_t)8 * LS) =
                make_float2(acc[mt][nt][2], acc[mt][nt][3]);
        }
}

// ---------------- softmax over l (in-place) ---------------------------------
__global__ void softmax_kernel(float* __restrict__ w)
{
    int row = blockIdx.x * 8 + (threadIdx.x >> 5);
    int lane = threadIdx.x & 31;
    float* p = w + (size_t)row * LS;
    float v[16];
    float m = -1e30f;
#pragma unroll
    for (int u = 0; u < 16; ++u) { v[u] = p[lane + u * 32]; m = fmaxf(m, v[u]); }
#pragma unroll
    for (int o = 16; o; o >>= 1) m = fmaxf(m, __shfl_xor_sync(0xffffffffu, m, o));
    float s = 0.f;
#pragma unroll
    for (int u = 0; u < 16; ++u) { v[u] = expf(v[u] - m); s += v[u]; }
#pragma unroll
    for (int o = 16; o; o >>= 1) s += __shfl_xor_sync(0xffffffffu, s, o);
    float inv = 1.f / s;
#pragma unroll
    for (int u = 0; u < 16; ++u) p[lane + u * 32] = v[u] * inv;
}

// ---------------- context: C[n][i][h] = sum_l w[n][i][l]*E[n][l][h] --------
__global__ __launch_bounds__(256) void ctx_kernel(const float* __restrict__ w)
{
    __shared__ float swt[64][36];
    __shared__ float se[32][68];
    int bid = blockIdx.x;
    int n = bid >> 4;
    int rr = bid & 15;
    int i0 = (rr >> 3) * 64, h0 = (rr & 7) * 64;
    int tid = threadIdx.x, tx = tid & 15, ty = tid >> 4;
    float acc[4][4];
#pragma unroll
    for (int i = 0; i < 4; i++)
#pragma unroll
        for (int h = 0; h < 4; h++) acc[i][h] = 0.f;

    for (int st = 0; st < 16; ++st) {
        int l0 = st * 32;
        for (int v = tid; v < 512; v += 256) {
            int r = v >> 3, c = (v & 7) * 4;
            *(float4*)&swt[r][c] =
                *(const float4*)(w + (size_t)(n * TT + i0 + r) * LS + l0 + c);
        }
        for (int v = tid; v < 512; v += 256) {
            int r = v >> 4, c = (v & 15) * 4;
            *(float4*)&se[r][c] =
                *(const float4*)(g_enc_out + (size_t)(n * LS + l0 + r) * HD + h0 + c);
        }
        __syncthreads();
#pragma unroll
        for (int k = 0; k < 32; ++k) {
            float wv[4], ev[4];
#pragma unroll
            for (int i = 0; i < 4; i++) wv[i] = swt[ty * 4 + i][k];
#pragma unroll
            for (int h = 0; h < 4; h++) ev[h] = se[k][tx * 4 + h];
#pragma unroll
            for (int i = 0; i < 4; i++)
#pragma unroll
                for (int h = 0; h < 4; h++)
                    acc[i][h] = fmaf(wv[i], ev[h], acc[i][h]);
        }
        __syncthreads();
    }
#pragma unroll
    for (int i = 0; i < 4; i++)
#pragma unroll
        for (int h = 0; h < 4; h++)
            g_ctx[(size_t)(n * TT + i0 + ty * 4 + i) * HD + h0 + tx * 4 + h] = acc[i][h];
}

// ---------------- ff ---------------------------------------------------------
__global__ __launch_bounds__(256) void ff_kernel(
    const float* __restrict__ W, const float* __restrict__ b)
{
    __shared__ float sa[64][36], swt[64][36];
    int bid = blockIdx.x;
    int m0 = (bid >> 3) * 64, o0 = (bid & 7) * 64;
    int tid = threadIdx.x, tx = tid & 15, ty = tid >> 4;
    float acc[4][4];
#pragma unroll
    for (int i = 0; i < 4; i++)
#pragma unroll
        for (int o = 0; o < 4; o++) acc[i][o] = 0.f;

    for (int st = 0; st < 32; ++st) {
        int k0 = st * 32;
        const float* A = (k0 < HD) ? g_Q : g_ctx;
        int koff = (k0 < HD) ? k0 : k0 - HD;
        for (int v = tid; v < 512; v += 256) {
            int r = v >> 3, c = (v & 7) * 4;
            *(float4*)&sa[r][c] = *(const float4*)(A + (size_t)(m0 + r) * HD + koff + c);
            *(float4*)&swt[r][c] = *(const float4*)(W + (size_t)(o0 + r) * (2 * HD) + k0 + c);
        }
        __syncthreads();
#pragma unroll
        for (int k = 0; k < 32; ++k) {
            float av[4], wv[4];
#pragma unroll
            for (int i = 0; i < 4; i++) av[i] = sa[ty * 4 + i][k];
#pragma unroll
            for (int o = 0; o < 4; o++) wv[o] = swt[tx * 4 + o][k];
#pragma unroll
            for (int i = 0; i < 4; i++)
#pragma unroll
                for (int o = 0; o < 4; o++)
                    acc[i][o] = fmaf(av[i], wv[o], acc[i][o]);
        }
        __syncthreads();
    }
#pragma unroll
    for (int i = 0; i < 4; i++)
#pragma unroll
        for (int o = 0; o < 4; o++)
            g_ff[(size_t)(m0 + ty * 4 + i) * HD + o0 + tx * 4 + o] = acc[i][o] + b[o0 + tx * 4 + o];
}

// ---------------- fc ---------------------------------------------------------
__global__ __launch_bounds__(256) void fc_kernel(
    const float* __restrict__ W, const float* __restrict__ b,
    float* __restrict__ vout)
{
    __shared__ float sa[128][36], swt[64][36];
    int m0 = blockIdx.x * 128;
    int tid = threadIdx.x, tx = tid & 15, ty = tid >> 4;
    float acc[8][4];
#pragma unroll
    for (int i = 0; i < 8; i++)
#pragma unroll
        for (int s = 0; s < 4; s++) acc[i][s] = 0.f;

    for (int st = 0; st < 16; ++st) {
        int k0 = st * 32;
        for (int v = tid; v < 1024; v += 256) {
            int r = v >> 3, c = (v & 7) * 4;
            *(float4*)&sa[r][c] = *(const float4*)(g_ff + (size_t)(m0 + r) * HD + k0 + c);
        }
        for (int v = tid; v < 512; v += 256) {
            int r = v >> 3, c = (v & 7) * 4;
            *(float4*)&swt[r][c] = *(const float4*)(W + (size_t)r * HD + k0 + c);
        }
        __syncthreads();
#pragma unroll
        for (int k = 0; k < 32; ++k) {
            float av[8], wv[4];
#pragma unroll
            for (int i = 0; i < 8; i++) av[i] = sa[ty * 8 + i][k];
#pragma unroll
            for (int s = 0; s < 4; s++) wv[s] = swt[tx * 4 + s][k];
#pragma unroll
            for (int i = 0; i < 8; i++)
#pragma unroll
                for (int s = 0; s < 4; s++)
                    acc[i][s] = fmaf(av[i], wv[s], acc[i][s]);
        }
        __syncthreads();
    }
#pragma unroll
    for (int i = 0; i < 8; i++)
#pragma unroll
        for (int s = 0; s < 4; s++)
            vout[(size_t)(m0 + ty * 8 + i) * SS + tx * 4 + s] = acc[i][s] + b[tx * 4 + s];
}

// ---------------- launch ----------------------------------------------------
extern "C" void kernel_launch(void* const* d_in, const int* in_sizes, int n_in,
                              void* d_out, int out_size)
{
    const float* x      = (const float*)d_in[0];
    const int*   target = (const int*)  d_in[1];
    const float* eWih   = (const float*)d_in[2];
    const float* eWhh   = (const float*)d_in[3];
    const float* ebih   = (const float*)d_in[4];
    const float* ebhh   = (const float*)d_in[5];
    const float* dWih   = (const float*)d_in[6];
    const float* dWhh   = (const float*)d_in[7];
    const float* dbih   = (const float*)d_in[8];
    const float* dbhh   = (const float*)d_in[9];
    const float* emb    = (const float*)d_in[10];
    const float* aW     = (const float*)d_in[11];
    const float* ab     = (const float*)d_in[12];
    const float* fW     = (const float*)d_in[13];
    const float* fb     = (const float*)d_in[14];

    float* out   = (float*)d_out;
    float* v_out = out;                       // (128,128,64)
    float* hN    = out + 1048576;             // (1,128,512)
    float* allw  = out + 1048576 + 65536;     // (128,128,512)

    init_enc_kernel<<<256, 256>>>();
    embproj_kernel<<<64, 256>>>(emb, dWih, dbih);
    enc_kernel<<<128, 256>>>(x, eWih, eWhh, ebih, ebhh);
    dec_kernel<<<128, 256>>>(target, dWhh, dbhh);
    copyh_kernel<<<256, 256>>>(hN);
    scores_kernel<<<1024, 256>>>(allw);
    softmax_kernel<<<2048, 256>>>(allw);
    ctx_kernel<<<2048, 256>>>(allw);
    ff_kernel<<<2048, 256>>>(aW, ab);
    fc_kernel<<<128, 256>>>(fW, fb, v_out);
}

// round 15
// speedup vs baseline: 1.4497x; 1.1378x over previous
#include <cuda_runtime.h>
#include <cuda_bf16.h>
#include <math.h>
#include <stdint.h>

// Problem constants
#define NB 128      // batch
#define HD 512      // hidden
#define LS 512      // source length
#define TT 128      // target length (MAXLEN)
#define SS 64       // num symbols
#define G3 1536     // 3*H

// ---------------- scratch (device globals; no allocation allowed) ----------
__device__ float          g_enc_out[NB * LS * HD];
__device__ __nv_bfloat16  g_eo_hi[NB * LS * HD];
__device__ __nv_bfloat16  g_eo_lo[NB * LS * HD];
__device__ float          g_h[NB * HD];
__device__ __nv_bfloat16  g_h_hi[NB * HD];
__device__ __nv_bfloat16  g_h_lo[NB * HD];
__device__ float          g_ghp[4 * NB * G3];   // split-K partials (4 slices)
__device__ float          g_embp[SS * G3];
__device__ float          g_Q[NB * TT * HD];
__device__ __nv_bfloat16  g_q_hi[NB * TT * HD];
__device__ __nv_bfloat16  g_q_lo[NB * TT * HD];
__device__ float          g_ctx[NB * TT * HD];
__device__ __nv_bfloat16  g_cx_hi[NB * TT * HD];
__device__ __nv_bfloat16  g_cx_lo[NB * TT * HD];
__device__ __nv_bfloat16  g_w_hi[NB * TT * LS];
__device__ __nv_bfloat16  g_w_lo[NB * TT * LS];
__device__ float          g_ff[NB * TT * HD];
__device__ unsigned       g_barc[1024];         // spread barrier counters

__device__ __forceinline__ float sigf(float v) { return 1.f / (1.f + expf(-v)); }

// Spread grid barrier (proven): 8 counters, 16 arrivals each.
__device__ __forceinline__ void gsync(unsigned* ctr, unsigned target) {
    __threadfence();
    __syncthreads();
    if (threadIdx.x == 0)
        atomicAdd(ctr + (blockIdx.x & 7) * 64, 1u);
    if (threadIdx.x < 8) {
        volatile unsigned* p = ctr + threadIdx.x * 64;
        while (*p < target) { }
    }
    __syncthreads();
    __threadfence();
}

// bf16 warp MMA m16n8k16, row.col, f32 accum (sm_80+ baseline PTX).
__device__ __forceinline__ void mma16816(float* d,
                                         uint32_t a0, uint32_t a1,
                                         uint32_t a2, uint32_t a3,
                                         uint32_t b0, uint32_t b1) {
    asm volatile(
        "mma.sync.aligned.m16n8k16.row.col.f32.bf16.bf16.f32 "
        "{%0,%1,%2,%3}, {%4,%5,%6,%7}, {%8,%9}, {%0,%1,%2,%3};"
        : "+f"(d[0]), "+f"(d[1]), "+f"(d[2]), "+f"(d[3])
        : "r"(a0), "r"(a1), "r"(a2), "r"(a3), "r"(b0), "r"(b1));
}

// ---------------- init kernel ----------------------------------------------
__global__ void init_enc_kernel() {
    int i = blockIdx.x * 256 + threadIdx.x;
    if (i < NB * HD) {
        g_h[i] = 0.f;
        g_h_hi[i] = __float2bfloat16(0.f);
        g_h_lo[i] = __float2bfloat16(0.f);
    }
    if (i < 1024) g_barc[i] = 0u;
}

// ---------------- emb_proj --------------------------------------------------
__global__ __launch_bounds__(256) void embproj_kernel(
    const float* __restrict__ emb, const float* __restrict__ Wih,
    const float* __restrict__ bih)
{
    __shared__ float se[HD];
    int s = blockIdx.x;
    for (int k = threadIdx.x; k < HD; k += 256) se[k] = emb[s * HD + k];
    __syncthreads();
    const float4* s4 = (const float4*)se;
    for (int j = threadIdx.x; j < G3; j += 256) {
        float a = bih[j];
        const float4* w4 = (const float4*)(Wih + j * HD);
        for (int k = 0; k < HD / 4; ++k) {
            float4 wv = w4[k];
            float4 sv = s4[k];
            a = fmaf(sv.x, wv.x, a);
            a = fmaf(sv.y, wv.y, a);
            a = fmaf(sv.z, wv.z, a);
            a = fmaf(sv.w, wv.w, a);
        }
        g_embp[s * G3 + j] = a;
    }
}

#define SW_STR 136
#define SH_STR 40

// stage one 32-k chunk of bf16 rows (stride 512) into smem [128][32] str 40
__device__ __forceinline__ void stage_h(__nv_bfloat16* dst,
                                        const __nv_bfloat16* __restrict__ src,
                                        int k0, int tid) {
    int n = tid >> 1, half = tid & 1;
    const uint4* s = (const uint4*)(src + n * HD + k0 + half * 16);
    uint4 v0 = __ldcg(s);
    uint4 v1 = __ldcg(s + 1);
    char* d = (char*)dst + n * (SH_STR * 2) + half * 32;
    *(uint4*)d = v0;
    *(uint4*)(d + 16) = v1;
}

// Shared recurrent GEMM body: partials into g_ghp. acc[mt][nt][4].
#define RNN_GEMM_BODY()                                                        \
    float acc[2][3][4];                                                        \
    _Pragma("unroll")                                                          \
    for (int mt = 0; mt < 2; ++mt)                                             \
        _Pragma("unroll")                                                      \
        for (int j = 0; j < 3; ++j)                                            \
            _Pragma("unroll")                                                  \
            for (int u = 0; u < 4; ++u) acc[mt][j][u] = 0.f;                   \
    stage_h(sHh, g_h_hi, kb, tid);                                             \
    stage_h(sHl, g_h_lo, kb, tid);                                             \
    __syncthreads();                                                           \
    _Pragma("unroll")                                                          \
    for (int c = 0; c < 4; ++c) {                                              \
        uint4 ph0, ph1, pl0, pl1;                                              \
        if (c < 3) {                                                           \
            int n_ = tid >> 1, half = tid & 1;                                 \
            const uint4* sh_ = (const uint4*)(g_h_hi + n_ * HD + kb +          \
                                              (c + 1) * 32 + half * 16);       \
            const uint4* sl_ = (const uint4*)(g_h_lo + n_ * HD + kb +          \
                                              (c + 1) * 32 + half * 16);       \
            ph0 = __ldcg(sh_); ph1 = __ldcg(sh_ + 1);                          \
            pl0 = __ldcg(sl_); pl1 = __ldcg(sl_ + 1);                          \
        }                                                                      \
        _Pragma("unroll")                                                      \
        for (int kk = 0; kk < 2; ++kk) {                                       \
            int kl = kk * 16 + q2;                                             \
            uint32_t ah[2][4], al[2][4];                                       \
            _Pragma("unroll")                                                  \
            for (int mt = 0; mt < 2; ++mt) {                                   \
                int r0 = mw * 32 + mt * 16 + gid;                              \
                ah[mt][0] = *(const uint32_t*)&sHh[r0 * SH_STR + kl];          \
                ah[mt][1] = *(const uint32_t*)&sHh[(r0 + 8) * SH_STR + kl];    \
                ah[mt][2] = *(const uint32_t*)&sHh[r0 * SH_STR + kl + 8];      \
                ah[mt][3] = *(const uint32_t*)&sHh[(r0 + 8) * SH_STR + kl + 8];\
                al[mt][0] = *(const uint32_t*)&sHl[r0 * SH_STR + kl];          \
                al[mt][1] = *(const uint32_t*)&sHl[(r0 + 8) * SH_STR + kl];    \
                al[mt][2] = *(const uint32_t*)&sHl[r0 * SH_STR + kl + 8];      \
                al[mt][3] = *(const uint32_t*)&sHl[(r0 + 8) * SH_STR + kl + 8];\
            }                                                                  \
            int kg = c * 32 + kk * 16 + q2;                                    \
            _Pragma("unroll")                                                  \
            for (int j = 0; j < 3; ++j) {                                      \
                int jr = nw * 24 + j * 8 + gid;                                \
                uint32_t bh0 = *(const uint32_t*)&sWh[jr * SW_STR + kg];       \
                uint32_t bh1 = *(const uint32_t*)&sWh[jr * SW_STR + kg + 8];   \
                uint32_t bl0 = *(const uint32_t*)&sWl[jr * SW_STR + kg];       \
                uint32_t bl1 = *(const uint32_t*)&sWl[jr * SW_STR + kg + 8];   \
                _Pragma("unroll")                                              \
                for (int mt = 0; mt < 2; ++mt) {                               \
                    mma16816(acc[mt][j], ah[mt][0], ah[mt][1], ah[mt][2],      \
                             ah[mt][3], bh0, bh1);                             \
                    mma16816(acc[mt][j], ah[mt][0], ah[mt][1], ah[mt][2],      \
                             ah[mt][3], bl0, bl1);                             \
                    mma16816(acc[mt][j], al[mt][0], al[mt][1], al[mt][2],      \
                             al[mt][3], bh0, bh1);                             \
                }                                                              \
            }                                                                  \
        }                                                                      \
        __syncthreads();                                                       \
        if (c < 3) {                                                           \
            int n_ = tid >> 1, half = tid & 1;                                 \
            char* dh = (char*)sHh + n_ * (SH_STR * 2) + half * 32;             \
            *(uint4*)dh = ph0; *(uint4*)(dh + 16) = ph1;                       \
            char* dl = (char*)sHl + n_ * (SH_STR * 2) + half * 32;             \
            *(uint4*)dl = pl0; *(uint4*)(dl + 16) = pl1;                       \
            __syncthreads();                                                   \
        }                                                                      \
    }                                                                          \
    _Pragma("unroll")                                                          \
    for (int mt = 0; mt < 2; ++mt)                                             \
        _Pragma("unroll")                                                      \
        for (int j = 0; j < 3; ++j) {                                          \
            int jr = nw * 24 + j * 8 + q2;                                     \
            int g = jr >> 4, jj = jr & 15;                                     \
            int n = mw * 32 + mt * 16 + gid;                                   \
            float* bp = g_ghp + (size_t)(ksl * NB + n) * G3 + g * HD + j0 + jj;\
            *(float2*)bp = make_float2(acc[mt][j][0], acc[mt][j][1]);          \
            *(float2*)(bp + 8 * G3) =                                          \
                make_float2(acc[mt][j][2], acc[mt][j][3]);                     \
        }

// weight conversion: fp32 Whh CTA slice -> hi/lo bf16 smem (48 jr x 128 k)
#define RNN_LOAD_W(WSRC)                                                       \
    _Pragma("unroll")                                                          \
    for (int it = 0; it < 24; ++it) {                                          \
        int idx = tid + it * 256;                                              \
        int r = idx >> 7, k = idx & 127;                                       \
        int g = r >> 4, jj = r & 15;                                           \
        float w = WSRC[(g * HD + j0 + jj) * HD + kb + k];                      \
        __nv_bfloat16 hi = __float2bfloat16(w);                                \
        __nv_bfloat16 lo = __float2bfloat16(w - __bfloat162float(hi));         \
        sWh[r * SW_STR + k] = hi;                                              \
        sWl[r * SW_STR + k] = lo;                                              \
    }

// ---------------- encoder persistent kernel --------------------------------
__global__ __launch_bounds__(256) void enc_kernel(
    const float* __restrict__ x, const float* __restrict__ Wih,
    const float* __restrict__ Whh, const float* __restrict__ bih,
    const float* __restrict__ bhh)
{
    __shared__ __nv_bfloat16 sWh[48 * SW_STR];
    __shared__ __nv_bfloat16 sWl[48 * SW_STR];
    __shared__ __nv_bfloat16 sHh[128 * SH_STR];
    __shared__ __nv_bfloat16 sHl[128 * SH_STR];

    const int tid = threadIdx.x;
    const int bid = blockIdx.x;
    const int wid = tid >> 5;
    const int lane = tid & 31;
    const int gid = lane >> 2;
    const int q2 = (lane & 3) * 2;
    const int mw = wid & 3;
    const int nw = wid >> 2;
    const int ksl = bid & 3;
    const int jb = bid >> 2;
    const int j0 = jb * 16, kb = ksl * 128;

    RNN_LOAD_W(Whh)
    __syncthreads();

    unsigned bt = 0;
    for (int t = 0; t < LS; ++t) {
        RNN_GEMM_BODY()
        bt += 16; gsync(g_barc, bt);

        int Gt = bid * 256 + tid;
#pragma unroll
        for (int e = 0; e < 2; ++e) {
            int idx = Gt + e * 32768;
            int n = idx >> 9, j = idx & 511;
            float x0 = x[(n * 2 + 0) * LS + t];
            float x1 = x[(n * 2 + 1) * LS + t];
            float ghr = bhh[j], ghz = bhh[HD + j], ghn = bhh[2 * HD + j];
#pragma unroll
            for (int q = 0; q < 4; ++q) {
                const float* p = g_ghp + (size_t)(q * NB + n) * G3 + j;
                ghr += __ldcg(p);
                ghz += __ldcg(p + HD);
                ghn += __ldcg(p + 2 * HD);
            }
            float gir = fmaf(x1, Wih[j * 2 + 1], fmaf(x0, Wih[j * 2], bih[j]));
            float giz = fmaf(x1, Wih[(HD + j) * 2 + 1],
                             fmaf(x0, Wih[(HD + j) * 2], bih[HD + j]));
            float gin = fmaf(x1, Wih[(2 * HD + j) * 2 + 1],
                             fmaf(x0, Wih[(2 * HD + j) * 2], bih[2 * HD + j]));
            float r = sigf(gir + ghr);
            float z = sigf(giz + ghz);
            float nn = tanhf(gin + r * ghn);
            float hold = __ldcg(g_h + n * HD + j);
            float hnew = (1.f - z) * nn + z * hold;
            g_h[n * HD + j] = hnew;
            __nv_bfloat16 hh = __float2bfloat16(hnew);
            __nv_bfloat16 hl = __float2bfloat16(hnew - __bfloat162float(hh));
            g_h_hi[n * HD + j] = hh;
            g_h_lo[n * HD + j] = hl;
            size_t eo = (size_t)(n * LS + t) * HD + j;
            g_enc_out[eo] = hnew;
            g_eo_hi[eo] = hh;
            g_eo_lo[eo] = hl;
        }
        bt += 16; gsync(g_barc, bt);
    }
}

// ---------------- decoder persistent kernel --------------------------------
__global__ __launch_bounds__(256) void dec_kernel(
    const int* __restrict__ target, const float* __restrict__ Whh,
    const float* __restrict__ bhh)
{
    __shared__ __nv_bfloat16 sWh[48 * SW_STR];
    __shared__ __nv_bfloat16 sWl[48 * SW_STR];
    __shared__ __nv_bfloat16 sHh[128 * SH_STR];
    __shared__ __nv_bfloat16 sHl[128 * SH_STR];

    const int tid = threadIdx.x;
    const int bid = blockIdx.x;
    const int wid = tid >> 5;
    const int lane = tid & 31;
    const int gid = lane >> 2;
    const int q2 = (lane & 3) * 2;
    const int mw = wid & 3;
    const int nw = wid >> 2;
    const int ksl = bid & 3;
    const int jb = bid >> 2;
    const int j0 = jb * 16, kb = ksl * 128;

    RNN_LOAD_W(Whh)
    __syncthreads();

    unsigned bt = 0;
    for (int t = 0; t < TT; ++t) {
        RNN_GEMM_BODY()
        bt += 16; gsync(g_barc + 512, bt);

        int Gt = bid * 256 + tid;
#pragma unroll
        for (int e = 0; e < 2; ++e) {
            int idx = Gt + e * 32768;
            int n = idx >> 9, j = idx & 511;
            int tok = (t == 0) ? 0 : target[n * TT + t - 1];
            const float* ep = g_embp + tok * G3;
            float gir = ep[j], giz = ep[HD + j], gin = ep[2 * HD + j];
            float ghr = bhh[j], ghz = bhh[HD + j], ghn = bhh[2 * HD + j];
#pragma unroll
            for (int q = 0; q < 4; ++q) {
                const float* p = g_ghp + (size_t)(q * NB + n) * G3 + j;
                ghr += __ldcg(p);
                ghz += __ldcg(p + HD);
                ghn += __ldcg(p + 2 * HD);
            }
            float r = sigf(gir + ghr);
            float z = sigf(giz + ghz);
            float nn = tanhf(gin + r * ghn);
            float hold = __ldcg(g_h + n * HD + j);
            float hnew = (1.f - z) * nn + z * hold;
            g_h[n * HD + j] = hnew;
            __nv_bfloat16 hh = __float2bfloat16(hnew);
            __nv_bfloat16 hl = __float2bfloat16(hnew - __bfloat162float(hh));
            g_h_hi[n * HD + j] = hh;
            g_h_lo[n * HD + j] = hl;
            size_t qo = (size_t)(n * TT + t) * HD + j;
            g_Q[qo] = hnew;
            g_q_hi[qo] = hh;
            g_q_lo[qo] = hl;
        }
        bt += 16; gsync(g_barc + 512, bt);
    }
}

// ---------------- dec_hN copy ----------------------------------------------
__global__ void copyh_kernel(float* __restrict__ dst) {
    int i = blockIdx.x * 256 + threadIdx.x;
    dst[i] = g_h[i];
}

// ---------------- scores via HMMA -------------------------------------------
__global__ __launch_bounds__(256) void scores_kernel(float* __restrict__ outw)
{
    __shared__ __nv_bfloat16 sAh[128 * SH_STR];
    __shared__ __nv_bfloat16 sAl[128 * SH_STR];
    __shared__ __nv_bfloat16 sBh[64 * SH_STR];
    __shared__ __nv_bfloat16 sBl[64 * SH_STR];

    const int tid = threadIdx.x;
    const int bid = blockIdx.x;
    const int n = bid >> 3;
    const int l0 = (bid & 7) * 64;
    const int wid = tid >> 5;
    const int lane = tid & 31;
    const int gid = lane >> 2;
    const int q2 = (lane & 3) * 2;
    const int mw = wid & 3;
    const int nw = wid >> 2;

    const __nv_bfloat16* Ah = g_q_hi + (size_t)n * TT * HD;
    const __nv_bfloat16* Al = g_q_lo + (size_t)n * TT * HD;
    const __nv_bfloat16* Bh = g_eo_hi + (size_t)(n * LS + l0) * HD;
    const __nv_bfloat16* Bl = g_eo_lo + (size_t)(n * LS + l0) * HD;

    float acc[2][4][4];
#pragma unroll
    for (int mt = 0; mt < 2; ++mt)
#pragma unroll
        for (int nt = 0; nt < 4; ++nt)
#pragma unroll
            for (int u = 0; u < 4; ++u) acc[mt][nt][u] = 0.f;

    for (int c = 0; c < 16; ++c) {
        int k0 = c * 32;
        stage_h(sAh, Ah, k0, tid);
        stage_h(sAl, Al, k0, tid);
        {
            int r = tid >> 2, q8 = (tid & 3) * 8;
            uint4 vh = __ldcg((const uint4*)(Bh + (size_t)r * HD + k0 + q8));
            uint4 vl = __ldcg((const uint4*)(Bl + (size_t)r * HD + k0 + q8));
            *(uint4*)((char*)sBh + r * (SH_STR * 2) + q8 * 2) = vh;
            *(uint4*)((char*)sBl + r * (SH_STR * 2) + q8 * 2) = vl;
        }
        __syncthreads();
#pragma unroll
        for (int kk = 0; kk < 2; ++kk) {
            int kl = kk * 16 + q2;
            uint32_t ah[2][4], al[2][4];
#pragma unroll
            for (int mt = 0; mt < 2; ++mt) {
                int r0 = mw * 32 + mt * 16 + gid;
                ah[mt][0] = *(const uint32_t*)&sAh[r0 * SH_STR + kl];
                ah[mt][1] = *(const uint32_t*)&sAh[(r0 + 8) * SH_STR + kl];
                ah[mt][2] = *(const uint32_t*)&sAh[r0 * SH_STR + kl + 8];
                ah[mt][3] = *(const uint32_t*)&sAh[(r0 + 8) * SH_STR + kl + 8];
                al[mt][0] = *(const uint32_t*)&sAl[r0 * SH_STR + kl];
                al[mt][1] = *(const uint32_t*)&sAl[(r0 + 8) * SH_STR + kl];
                al[mt][2] = *(const uint32_t*)&sAl[r0 * SH_STR + kl + 8];
                al[mt][3] = *(const uint32_t*)&sAl[(r0 + 8) * SH_STR + kl + 8];
            }
#pragma unroll
            for (int nt = 0; nt < 4; ++nt) {
                int lr = nw * 32 + nt * 8 + gid;
                uint32_t bh0 = *(const uint32_t*)&sBh[lr * SH_STR + kl];
                uint32_t bh1 = *(const uint32_t*)&sBh[lr * SH_STR + kl + 8];
                uint32_t bl0 = *(const uint32_t*)&sBl[lr * SH_STR + kl];
                uint32_t bl1 = *(const uint32_t*)&sBl[lr * SH_STR + kl + 8];
#pragma unroll
                for (int mt = 0; mt < 2; ++mt) {
                    mma16816(acc[mt][nt], ah[mt][0], ah[mt][1], ah[mt][2],
                             ah[mt][3], bh0, bh1);
                    mma16816(acc[mt][nt], ah[mt][0], ah[mt][1], ah[mt][2],
                             ah[mt][3], bl0, bl1);
                    mma16816(acc[mt][nt], al[mt][0], al[mt][1], al[mt][2],
                             al[mt][3], bh0, bh1);
                }
            }
        }
        __syncthreads();
    }
#pragma unroll
    for (int mt = 0; mt < 2; ++mt)
#pragma unroll
        for (int nt = 0; nt < 4; ++nt) {
            int i = mw * 32 + mt * 16 + gid;
            int l = l0 + nw * 32 + nt * 8 + q2;
            float* op = outw + (size_t)(n * TT + i) * LS + l;
            *(float2*)op = make_float2(acc[mt][nt][0], acc[mt][nt][1]);
            *(float2*)(op + (size_t)8 * LS) =
                make_float2(acc[mt][nt][2], acc[mt][nt][3]);
        }
}

// ---------------- softmax (in-place) + hi/lo emission -----------------------
__global__ void softmax_kernel(float* __restrict__ w)
{
    int row = blockIdx.x * 8 + (threadIdx.x >> 5);
    int lane = threadIdx.x & 31;
    float* p = w + (size_t)row * LS;
    __nv_bfloat16* ph = g_w_hi + (size_t)row * LS;
    __nv_bfloat16* pl = g_w_lo + (size_t)row * LS;
    float v[16];
    float m = -1e30f;
#pragma unroll
    for (int u = 0; u < 16; ++u) { v[u] = p[lane + u * 32]; m = fmaxf(m, v[u]); }
#pragma unroll
    for (int o = 16; o; o >>= 1) m = fmaxf(m, __shfl_xor_sync(0xffffffffu, m, o));
    float s = 0.f;
#pragma unroll
    for (int u = 0; u < 16; ++u) { v[u] = expf(v[u] - m); s += v[u]; }
#pragma unroll
    for (int o = 16; o; o >>= 1) s += __shfl_xor_sync(0xffffffffu, s, o);
    float inv = 1.f / s;
#pragma unroll
    for (int u = 0; u < 16; ++u) {
        float val = v[u] * inv;
        p[lane + u * 32] = val;
        __nv_bfloat16 hh = __float2bfloat16(val);
        ph[lane + u * 32] = hh;
        pl[lane + u * 32] = __float2bfloat16(val - __bfloat162float(hh));
    }
}

// ---------------- ctx via HMMA: C[n][i][h] = sum_l w·E ----------------------
__global__ __launch_bounds__(256) void ctx_kernel(const float* __restrict__ wdummy)
{
    __shared__ __nv_bfloat16 sAh[128 * SH_STR];
    __shared__ __nv_bfloat16 sAl[128 * SH_STR];
    __shared__ __nv_bfloat16 sBh[64 * SH_STR];
    __shared__ __nv_bfloat16 sBl[64 * SH_STR];

    const int tid = threadIdx.x;
    const int bid = blockIdx.x;
    const int n = bid >> 3;
    const int h0 = (bid & 7) * 64;
    const int wid = tid >> 5;
    const int lane = tid & 31;
    const int gid = lane >> 2;
    const int q2 = (lane & 3) * 2;
    const int mw = wid & 3;
    const int nw = wid >> 2;

    const __nv_bfloat16* Ah = g_w_hi + (size_t)n * TT * LS;
    const __nv_bfloat16* Al = g_w_lo + (size_t)n * TT * LS;

    float acc[2][4][4];
#pragma unroll
    for (int mt = 0; mt < 2; ++mt)
#pragma unroll
        for (int nt = 0; nt < 4; ++nt)
#pragma unroll
            for (int u = 0; u < 4; ++u) acc[mt][nt][u] = 0.f;

    for (int c = 0; c < 16; ++c) {
        int k0 = c * 32;                 // l chunk
        stage_h(sAh, Ah, k0, tid);
        stage_h(sAl, Al, k0, tid);
        {
            int r = tid >> 3, hc = (tid & 7) * 8;
            size_t base = (size_t)(n * LS + k0 + r) * HD + h0 + hc;
            uint4 vh = __ldcg((const uint4*)(g_eo_hi + base));
            uint4 vl = __ldcg((const uint4*)(g_eo_lo + base));
            const __nv_bfloat16* eh = (const __nv_bfloat16*)&vh;
            const __nv_bfloat16* el = (const __nv_bfloat16*)&vl;
#pragma unroll
            for (int u = 0; u < 8; ++u) {
                sBh[(hc + u) * SH_STR + r] = eh[u];
                sBl[(hc + u) * SH_STR + r] = el[u];
            }
        }
        __syncthreads();
#pragma unroll
        for (int kk = 0; kk < 2; ++kk) {
            int kl = kk * 16 + q2;
            uint32_t ah[2][4], al[2][4];
#pragma unroll
            for (int mt = 0; mt < 2; ++mt) {
                int r0 = mw * 32 + mt * 16 + gid;
                ah[mt][0] = *(const uint32_t*)&sAh[r0 * SH_STR + kl];
                ah[mt][1] = *(const uint32_t*)&sAh[(r0 + 8) * SH_STR + kl];
                ah[mt][2] = *(const uint32_t*)&sAh[r0 * SH_STR + kl + 8];
                ah[mt][3] = *(const uint32_t*)&sAh[(r0 + 8) * SH_STR + kl + 8];
                al[mt][0] = *(const uint32_t*)&sAl[r0 * SH_STR + kl];
                al[mt][1] = *(const uint32_t*)&sAl[(r0 + 8) * SH_STR + kl];
                al[mt][2] = *(const uint32_t*)&sAl[r0 * SH_STR + kl + 8];
                al[mt][3] = *(const uint32_t*)&sAl[(r0 + 8) * SH_STR + kl + 8];
            }
#pragma unroll
            for (int nt = 0; nt < 4; ++nt) {
                int hr = nw * 32 + nt * 8 + gid;
                uint32_t bh0 = *(const uint32_t*)&sBh[hr * SH_STR + kl];
                uint32_t bh1 = *(const uint32_t*)&sBh[hr * SH_STR + kl + 8];
                uint32_t bl0 = *(const uint32_t*)&sBl[hr * SH_STR + kl];
                uint32_t bl1 = *(const uint32_t*)&sBl[hr * SH_STR + kl + 8];
#pragma unroll
                for (int mt = 0; mt < 2; ++mt) {
                    mma16816(acc[mt][nt], ah[mt][0], ah[mt][1], ah[mt][2],
                             ah[mt][3], bh0, bh1);
                    mma16816(acc[mt][nt], ah[mt][0], ah[mt][1], ah[mt][2],
                             ah[mt][3], bl0, bl1);
                    mma16816(acc[mt][nt], al[mt][0], al[mt][1], al[mt][2],
                             al[mt][3], bh0, bh1);
                }
            }
        }
        __syncthreads();
    }
#pragma unroll
    for (int mt = 0; mt < 2; ++mt)
#pragma unroll
        for (int nt = 0; nt < 4; ++nt) {
            int i = mw * 32 + mt * 16 + gid;
            int h = h0 + nw * 32 + nt * 8 + q2;
#pragma unroll
            for (int rr = 0; rr < 2; ++rr) {
                float v0 = acc[mt][nt][rr * 2 + 0];
                float v1 = acc[mt][nt][rr * 2 + 1];
                size_t o = (size_t)(n * TT + i + rr * 8) * HD + h;
                *(float2*)(g_ctx + o) = make_float2(v0, v1);
                __nv_bfloat16 h0b = __float2bfloat16(v0);
                __nv_bfloat16 h1b = __float2bfloat16(v1);
                __nv_bfloat162 hv; hv.x = h0b; hv.y = h1b;
                *(__nv_bfloat162*)(g_cx_hi + o) = hv;
                __nv_bfloat162 lv;
                lv.x = __float2bfloat16(v0 - __bfloat162float(h0b));
                lv.y = __float2bfloat16(v1 - __bfloat162float(h1b));
                *(__nv_bfloat162*)(g_cx_lo + o) = lv;
            }
        }
}

// ---------------- ff via HMMA: g_ff = [Q|ctx] @ W^T + b ---------------------
__global__ __launch_bounds__(256) void ff_kernel(
    const float* __restrict__ W, const float* __restrict__ b)
{
    __shared__ __nv_bfloat16 sAh[128 * SH_STR];
    __shared__ __nv_bfloat16 sAl[128 * SH_STR];
    __shared__ __nv_bfloat16 sBh[64 * SH_STR];
    __shared__ __nv_bfloat16 sBl[64 * SH_STR];

    const int tid = threadIdx.x;
    const int bid = blockIdx.x;
    const int m0 = (bid >> 3) * 128;
    const int o0 = (bid & 7) * 64;
    const int wid = tid >> 5;
    const int lane = tid & 31;
    const int gid = lane >> 2;
    const int q2 = (lane & 3) * 2;
    const int mw = wid & 3;
    const int nw = wid >> 2;

    float acc[2][4][4];
#pragma unroll
    for (int mt = 0; mt < 2; ++mt)
#pragma unroll
        for (int nt = 0; nt < 4; ++nt)
#pragma unroll
            for (int u = 0; u < 4; ++u) acc[mt][nt][u] = 0.f;

    for (int c = 0; c < 32; ++c) {
        int k0 = c * 32;
        const __nv_bfloat16* Ah =
            (k0 < HD) ? (g_q_hi + (size_t)m0 * HD) : (g_cx_hi + (size_t)m0 * HD);
        const __nv_bfloat16* Al =
            (k0 < HD) ? (g_q_lo + (size_t)m0 * HD) : (g_cx_lo + (size_t)m0 * HD);
        int koff = (k0 < HD) ? k0 : k0 - HD;
        stage_h(sAh, Ah, koff, tid);
        stage_h(sAl, Al, koff, tid);
        {
            int r = tid >> 2, q8 = (tid & 3) * 8;
            const float4* wp = (const float4*)(W + (size_t)(o0 + r) * (2 * HD) + k0 + q8);
            float4 w0 = __ldcg(wp);
            float4 w1 = __ldcg(wp + 1);
            float wv[8] = {w0.x, w0.y, w0.z, w0.w, w1.x, w1.y, w1.z, w1.w};
#pragma unroll
            for (int u = 0; u < 8; u += 2) {
                __nv_bfloat16 h0b = __float2bfloat16(wv[u]);
                __nv_bfloat16 h1b = __float2bfloat16(wv[u + 1]);
                __nv_bfloat162 hv; hv.x = h0b; hv.y = h1b;
                *(__nv_bfloat162*)&sBh[r * SH_STR + q8 + u] = hv;
                __nv_bfloat162 lv;
                lv.x = __float2bfloat16(wv[u] - __bfloat162float(h0b));
                lv.y = __float2bfloat16(wv[u + 1] - __bfloat162float(h1b));
                *(__nv_bfloat162*)&sBl[r * SH_STR + q8 + u] = lv;
            }
        }
        __syncthreads();
#pragma unroll
        for (int kk = 0; kk < 2; ++kk) {
            int kl = kk * 16 + q2;
            uint32_t ah[2][4], al[2][4];
#pragma unroll
            for (int mt = 0; mt < 2; ++mt) {
                int r0 = mw * 32 + mt * 16 + gid;
                ah[mt][0] = *(const uint32_t*)&sAh[r0 * SH_STR + kl];
                ah[mt][1] = *(const uint32_t*)&sAh[(r0 + 8) * SH_STR + kl];
                ah[mt][2] = *(const uint32_t*)&sAh[r0 * SH_STR + kl + 8];
                ah[mt][3] = *(const uint32_t*)&sAh[(r0 + 8) * SH_STR + kl + 8];
                al[mt][0] = *(const uint32_t*)&sAl[r0 * SH_STR + kl];
                al[mt][1] = *(const uint32_t*)&sAl[(r0 + 8) * SH_STR + kl];
                al[mt][2] = *(const uint32_t*)&sAl[r0 * SH_STR + kl + 8];
                al[mt][3] = *(const uint32_t*)&sAl[(r0 + 8) * SH_STR + kl + 8];
            }
#pragma unroll
            for (int nt = 0; nt < 4; ++nt) {
                int orow = nw * 32 + nt * 8 + gid;
                uint32_t bh0 = *(const uint32_t*)&sBh[orow * SH_STR + kl];
                uint32_t bh1 = *(const uint32_t*)&sBh[orow * SH_STR + kl + 8];
                uint32_t bl0 = *(const uint32_t*)&sBl[orow * SH_STR + kl];
                uint32_t bl1 = *(const uint32_t*)&sBl[orow * SH_STR + kl + 8];
#pragma unroll
                for (int mt = 0; mt < 2; ++mt) {
                    mma16816(acc[mt][nt], ah[mt][0], ah[mt][1], ah[mt][2],
                             ah[mt][3], bh0, bh1);
                    mma16816(acc[mt][nt], ah[mt][0], ah[mt][1], ah[mt][2],
                             ah[mt][3], bl0, bl1);
                    mma16816(acc[mt][nt], al[mt][0], al[mt][1], al[mt][2],
                             al[mt][3], bh0, bh1);
                }
            }
        }
        __syncthreads();
    }
#pragma unroll
    for (int mt = 0; mt < 2; ++mt)
#pragma unroll
        for (int nt = 0; nt < 4; ++nt) {
            int i = mw * 32 + mt * 16 + gid;
            int o = o0 + nw * 32 + nt * 8 + q2;
            float b0 = b[o], b1 = b[o + 1];
            float* op = g_ff + (size_t)(m0 + i) * HD + o;
            *(float2*)op = make_float2(acc[mt][nt][0] + b0, acc[mt][nt][1] + b1);
            *(float2*)(op + (size_t)8 * HD) =
                make_float2(acc[mt][nt][2] + b0, acc[mt][nt][3] + b1);
        }
}

// ---------------- fc ---------------------------------------------------------
__global__ __launch_bounds__(256) void fc_kernel(
    const float* __restrict__ W, const float* __restrict__ b,
    float* __restrict__ vout)
{
    __shared__ float sa[128][36], swt[64][36];
    int m0 = blockIdx.x * 128;
    int tid = threadIdx.x, tx = tid & 15, ty = tid >> 4;
    float acc[8][4];
#pragma unroll
    for (int i = 0; i < 8; i++)
#pragma unroll
        for (int s = 0; s < 4; s++) acc[i][s] = 0.f;

    for (int st = 0; st < 16; ++st) {
        int k0 = st * 32;
        for (int v = tid; v < 1024; v += 256) {
            int r = v >> 3, c = (v & 7) * 4;
            *(float4*)&sa[r][c] = *(const float4*)(g_ff + (size_t)(m0 + r) * HD + k0 + c);
        }
        for (int v = tid; v < 512; v += 256) {
            int r = v >> 3, c = (v & 7) * 4;
            *(float4*)&swt[r][c] = *(const float4*)(W + (size_t)r * HD + k0 + c);
        }
        __syncthreads();
#pragma unroll
        for (int k = 0; k < 32; ++k) {
            float av[8], wv[4];
#pragma unroll
            for (int i = 0; i < 8; i++) av[i] = sa[ty * 8 + i][k];
#pragma unroll
            for (int s = 0; s < 4; s++) wv[s] = swt[tx * 4 + s][k];
#pragma unroll
            for (int i = 0; i < 8; i++)
#pragma unroll
                for (int s = 0; s < 4; s++)
                    acc[i][s] = fmaf(av[i], wv[s], acc[i][s]);
        }
        __syncthreads();
    }
#pragma unroll
    for (int i = 0; i < 8; i++)
#pragma unroll
        for (int s = 0; s < 4; s++)
            vout[(size_t)(m0 + ty * 8 + i) * SS + tx * 4 + s] = acc[i][s] + b[tx * 4 + s];
}

// ---------------- launch ----------------------------------------------------
extern "C" void kernel_launch(void* const* d_in, const int* in_sizes, int n_in,
                              void* d_out, int out_size)
{
    const float* x      = (const float*)d_in[0];
    const int*   target = (const int*)  d_in[1];
    const float* eWih   = (const float*)d_in[2];
    const float* eWhh   = (const float*)d_in[3];
    const float* ebih   = (const float*)d_in[4];
    const float* ebhh   = (const float*)d_in[5];
    const float* dWih   = (const float*)d_in[6];
    const float* dWhh   = (const float*)d_in[7];
    const float* dbih   = (const float*)d_in[8];
    const float* dbhh   = (const float*)d_in[9];
    const float* emb    = (const float*)d_in[10];
    const float* aW     = (const float*)d_in[11];
    const float* ab     = (const float*)d_in[12];
    const float* fW     = (const float*)d_in[13];
    const float* fb     = (const float*)d_in[14];

    float* out   = (float*)d_out;
    float* v_out = out;                       // (128,128,64)
    float* hN    = out + 1048576;             // (1,128,512)
    float* allw  = out + 1048576 + 65536;     // (128,128,512)

    init_enc_kernel<<<256, 256>>>();
    embproj_kernel<<<64, 256>>>(emb, dWih, dbih);
    enc_kernel<<<128, 256>>>(x, eWih, eWhh, ebih, ebhh);
    dec_kernel<<<128, 256>>>(target, dWhh, dbhh);
    copyh_kernel<<<256, 256>>>(hN);
    scores_kernel<<<1024, 256>>>(allw);
    softmax_kernel<<<2048, 256>>>(allw);
    ctx_kernel<<<1024, 256>>>(allw);
    ff_kernel<<<1024, 256>>>(aW, ab);
    fc_kernel<<<128, 256>>>(fW, fb, v_out);
}

// round 16
// speedup vs baseline: 1.6089x; 1.1098x over previous
#include <cuda_runtime.h>
#include <cuda_bf16.h>
#include <math.h>
#include <stdint.h>

// Problem constants
#define NB 128      // batch
#define HD 512      // hidden
#define LS 512      // source length
#define TT 128      // target length (MAXLEN)
#define SS 64       // num symbols
#define G3 1536     // 3*H

// ---------------- scratch (device globals; no allocation allowed) ----------
__device__ __nv_bfloat16  g_eo_hi[NB * LS * HD];
__device__ __nv_bfloat16  g_eo_lo[NB * LS * HD];
__device__ __nv_bfloat16  g_h_hi[NB * HD];
__device__ __nv_bfloat16  g_h_lo[NB * HD];
__device__ float          g_ghp[4 * NB * G3];   // split-K partials (4 slices)
__device__ float          g_embp[SS * G3];
__device__ __nv_bfloat16  g_q_hi[NB * TT * HD];
__device__ __nv_bfloat16  g_q_lo[NB * TT * HD];
__device__ __nv_bfloat16  g_cx_hi[NB * TT * HD];
__device__ __nv_bfloat16  g_cx_lo[NB * TT * HD];
__device__ __nv_bfloat16  g_w_hi[NB * TT * LS];
__device__ __nv_bfloat16  g_w_lo[NB * TT * LS];
__device__ float          g_ff[NB * TT * HD];
__device__ unsigned       g_barc[1024];         // spread barrier counters

__device__ __forceinline__ float sigf(float v) { return 1.f / (1.f + expf(-v)); }

// Spread grid barrier, CG-style release/acquire (no per-thread membar):
// CTA stores -> bar.sync -> tid0 red.release.gpu arrival; 8 lanes poll with
// ld.acquire.gpu (one counter each, 256B apart); bar.sync.
__device__ __forceinline__ void gsync(unsigned* ctr, unsigned target) {
    __syncthreads();
    if (threadIdx.x == 0) {
        unsigned* a = ctr + (blockIdx.x & 7) * 64;
        asm volatile("red.release.gpu.global.add.u32 [%0], 1;"
                     :: "l"(a) : "memory");
    }
    if (threadIdx.x < 8) {
        unsigned* p = ctr + threadIdx.x * 64;
        unsigned v;
        do {
            asm volatile("ld.acquire.gpu.global.u32 %0, [%1];"
                         : "=r"(v) : "l"(p) : "memory");
        } while (v < target);
    }
    __syncthreads();
}

// bf16 warp MMA m16n8k16, row.col, f32 accum (sm_80+ baseline PTX).
__device__ __forceinline__ void mma16816(float* d,
                                         uint32_t a0, uint32_t a1,
                                         uint32_t a2, uint32_t a3,
                                         uint32_t b0, uint32_t b1) {
    asm volatile(
        "mma.sync.aligned.m16n8k16.row.col.f32.bf16.bf16.f32 "
        "{%0,%1,%2,%3}, {%4,%5,%6,%7}, {%8,%9}, {%0,%1,%2,%3};"
        : "+f"(d[0]), "+f"(d[1]), "+f"(d[2]), "+f"(d[3])
        : "r"(a0), "r"(a1), "r"(a2), "r"(a3), "r"(b0), "r"(b1));
}

// ---------------- init kernel ----------------------------------------------
__global__ void init_enc_kernel() {
    int i = blockIdx.x * 256 + threadIdx.x;
    if (i < NB * HD) {
        g_h_hi[i] = __float2bfloat16(0.f);
        g_h_lo[i] = __float2bfloat16(0.f);
    }
    if (i < 1024) g_barc[i] = 0u;
}

// ---------------- emb_proj --------------------------------------------------
__global__ __launch_bounds__(256) void embproj_kernel(
    const float* __restrict__ emb, const float* __restrict__ Wih,
    const float* __restrict__ bih)
{
    __shared__ float se[HD];
    int s = blockIdx.x;
    for (int k = threadIdx.x; k < HD; k += 256) se[k] = emb[s * HD + k];
    __syncthreads();
    const float4* s4 = (const float4*)se;
    for (int j = threadIdx.x; j < G3; j += 256) {
        float a = bih[j];
        const float4* w4 = (const float4*)(Wih + j * HD);
        for (int k = 0; k < HD / 4; ++k) {
            float4 wv = w4[k];
            float4 sv = s4[k];
            a = fmaf(sv.x, wv.x, a);
            a = fmaf(sv.y, wv.y, a);
            a = fmaf(sv.z, wv.z, a);
            a = fmaf(sv.w, wv.w, a);
        }
        g_embp[s * G3 + j] = a;
    }
}

#define SW_STR 136
#define SH_STR 40

// stage one 32-k chunk of bf16 rows (stride 512) into smem [128][32] str 40
__device__ __forceinline__ void stage_h(__nv_bfloat16* dst,
                                        const __nv_bfloat16* __restrict__ src,
                                        int k0, int tid) {
    int n = tid >> 1, half = tid & 1;
    const uint4* s = (const uint4*)(src + n * HD + k0 + half * 16);
    uint4 v0 = __ldcg(s);
    uint4 v1 = __ldcg(s + 1);
    char* d = (char*)dst + n * (SH_STR * 2) + half * 32;
    *(uint4*)d = v0;
    *(uint4*)(d + 16) = v1;
}

// Shared recurrent GEMM body: partials into g_ghp. acc[mt][nt][4].
#define RNN_GEMM_BODY()                                                        \
    float acc[2][3][4];                                                        \
    _Pragma("unroll")                                                          \
    for (int mt = 0; mt < 2; ++mt)                                             \
        _Pragma("unroll")                                                      \
        for (int j = 0; j < 3; ++j)                                            \
            _Pragma("unroll")                                                  \
            for (int u = 0; u < 4; ++u) acc[mt][j][u] = 0.f;                   \
    stage_h(sHh, g_h_hi, kb, tid);                                             \
    stage_h(sHl, g_h_lo, kb, tid);                                             \
    __syncthreads();                                                           \
    _Pragma("unroll")                                                          \
    for (int c = 0; c < 4; ++c) {                                              \
        uint4 ph0, ph1, pl0, pl1;                                              \
        if (c < 3) {                                                           \
            int n_ = tid >> 1, half = tid & 1;                                 \
            const uint4* sh_ = (const uint4*)(g_h_hi + n_ * HD + kb +          \
                                              (c + 1) * 32 + half * 16);       \
            const uint4* sl_ = (const uint4*)(g_h_lo + n_ * HD + kb +          \
                                              (c + 1) * 32 + half * 16);       \
            ph0 = __ldcg(sh_); ph1 = __ldcg(sh_ + 1);                          \
            pl0 = __ldcg(sl_); pl1 = __ldcg(sl_ + 1);                          \
        }                                                                      \
        _Pragma("unroll")                                                      \
        for (int kk = 0; kk < 2; ++kk) {                                       \
            int kl = kk * 16 + q2;                                             \
            uint32_t ah[2][4], al[2][4];                                       \
            _Pragma("unroll")                                                  \
            for (int mt = 0; mt < 2; ++mt) {                                   \
                int r0 = mw * 32 + mt * 16 + gid;                              \
                ah[mt][0] = *(const uint32_t*)&sHh[r0 * SH_STR + kl];          \
                ah[mt][1] = *(const uint32_t*)&sHh[(r0 + 8) * SH_STR + kl];    \
                ah[mt][2] = *(const uint32_t*)&sHh[r0 * SH_STR + kl + 8];      \
                ah[mt][3] = *(const uint32_t*)&sHh[(r0 + 8) * SH_STR + kl + 8];\
                al[mt][0] = *(const uint32_t*)&sHl[r0 * SH_STR + kl];          \
                al[mt][1] = *(const uint32_t*)&sHl[(r0 + 8) * SH_STR + kl];    \
                al[mt][2] = *(const uint32_t*)&sHl[r0 * SH_STR + kl + 8];      \
                al[mt][3] = *(const uint32_t*)&sHl[(r0 + 8) * SH_STR + kl + 8];\
            }                                                                  \
            int kg = c * 32 + kk * 16 + q2;                                    \
            _Pragma("unroll")                                                  \
            for (int j = 0; j < 3; ++j) {                                      \
                int jr = nw * 24 + j * 8 + gid;                                \
                uint32_t bh0 = *(const uint32_t*)&sWh[jr * SW_STR + kg];       \
                uint32_t bh1 = *(const uint32_t*)&sWh[jr * SW_STR + kg + 8];   \
                uint32_t bl0 = *(const uint32_t*)&sWl[jr * SW_STR + kg];       \
                uint32_t bl1 = *(const uint32_t*)&sWl[jr * SW_STR + kg + 8];   \
                _Pragma("unroll")                                              \
                for (int mt = 0; mt < 2; ++mt) {                               \
                    mma16816(acc[mt][j], ah[mt][0], ah[mt][1], ah[mt][2],      \
                             ah[mt][3], bh0, bh1);                             \
                    mma16816(acc[mt][j], ah[mt][0], ah[mt][1], ah[mt][2],      \
                             ah[mt][3], bl0, bl1);                             \
                    mma16816(acc[mt][j], al[mt][0], al[mt][1], al[mt][2],      \
                             al[mt][3], bh0, bh1);                             \
                }                                                              \
            }                                                                  \
        }                                                                      \
        __syncthreads();                                                       \
        if (c < 3) {                                                           \
            int n_ = tid >> 1, half = tid & 1;                                 \
            char* dh = (char*)sHh + n_ * (SH_STR * 2) + half * 32;             \
            *(uint4*)dh = ph0; *(uint4*)(dh + 16) = ph1;                       \
            char* dl = (char*)sHl + n_ * (SH_STR * 2) + half * 32;             \
            *(uint4*)dl = pl0; *(uint4*)(dl + 16) = pl1;                       \
            __syncthreads();                                                   \
        }                                                                      \
    }                                                                          \
    _Pragma("unroll")                                                          \
    for (int mt = 0; mt < 2; ++mt)                                             \
        _Pragma("unroll")                                                      \
        for (int j = 0; j < 3; ++j) {                                          \
            int jr = nw * 24 + j * 8 + q2;                                     \
            int g = jr >> 4, jj = jr & 15;                                     \
            int n = mw * 32 + mt * 16 + gid;                                   \
            float* bp = g_ghp + (size_t)(ksl * NB + n) * G3 + g * HD + j0 + jj;\
            *(float2*)bp = make_float2(acc[mt][j][0], acc[mt][j][1]);          \
            *(float2*)(bp + 8 * G3) =                                          \
                make_float2(acc[mt][j][2], acc[mt][j][3]);                     \
        }

// weight conversion: fp32 Whh CTA slice -> hi/lo bf16 smem (48 jr x 128 k)
#define RNN_LOAD_W(WSRC)                                                       \
    _Pragma("unroll")                                                          \
    for (int it = 0; it < 24; ++it) {                                          \
        int idx = tid + it * 256;                                              \
        int r = idx >> 7, k = idx & 127;                                       \
        int g = r >> 4, jj = r & 15;                                           \
        float w = WSRC[(g * HD + j0 + jj) * HD + kb + k];                      \
        __nv_bfloat16 hi = __float2bfloat16(w);                                \
        __nv_bfloat16 lo = __float2bfloat16(w - __bfloat162float(hi));         \
        sWh[r * SW_STR + k] = hi;                                              \
        sWl[r * SW_STR + k] = lo;                                              \
    }

// ---------------- encoder persistent kernel --------------------------------
__global__ __launch_bounds__(256) void enc_kernel(
    const float* __restrict__ x, const float* __restrict__ Wih,
    const float* __restrict__ Whh, const float* __restrict__ bih,
    const float* __restrict__ bhh)
{
    __shared__ __nv_bfloat16 sWh[48 * SW_STR];
    __shared__ __nv_bfloat16 sWl[48 * SW_STR];
    __shared__ __nv_bfloat16 sHh[128 * SH_STR];
    __shared__ __nv_bfloat16 sHl[128 * SH_STR];

    const int tid = threadIdx.x;
    const int bid = blockIdx.x;
    const int wid = tid >> 5;
    const int lane = tid & 31;
    const int gid = lane >> 2;
    const int q2 = (lane & 3) * 2;
    const int mw = wid & 3;
    const int nw = wid >> 2;
    const int ksl = bid & 3;
    const int jb = bid >> 2;
    const int j0 = jb * 16, kb = ksl * 128;

    RNN_LOAD_W(Whh)
    __syncthreads();

    unsigned bt = 0;
    for (int t = 0; t < LS; ++t) {
        RNN_GEMM_BODY()
        bt += 16; gsync(g_barc, bt);

        int Gt = bid * 256 + tid;
#pragma unroll
        for (int e = 0; e < 2; ++e) {
            int idx = Gt + e * 32768;
            int n = idx >> 9, j = idx & 511;
            float x0 = x[(n * 2 + 0) * LS + t];
            float x1 = x[(n * 2 + 1) * LS + t];
            float ghr = bhh[j], ghz = bhh[HD + j], ghn = bhh[2 * HD + j];
#pragma unroll
            for (int q = 0; q < 4; ++q) {
                const float* p = g_ghp + (size_t)(q * NB + n) * G3 + j;
                ghr += __ldcg(p);
                ghz += __ldcg(p + HD);
                ghn += __ldcg(p + 2 * HD);
            }
            float gir = fmaf(x1, Wih[j * 2 + 1], fmaf(x0, Wih[j * 2], bih[j]));
            float giz = fmaf(x1, Wih[(HD + j) * 2 + 1],
                             fmaf(x0, Wih[(HD + j) * 2], bih[HD + j]));
            float gin = fmaf(x1, Wih[(2 * HD + j) * 2 + 1],
                             fmaf(x0, Wih[(2 * HD + j) * 2], bih[2 * HD + j]));
            float r = sigf(gir + ghr);
            float z = sigf(giz + ghz);
            float nn = tanhf(gin + r * ghn);
            float hold = __bfloat162float(g_h_hi[n * HD + j]) +
                         __bfloat162float(g_h_lo[n * HD + j]);
            float hnew = (1.f - z) * nn + z * hold;
            __nv_bfloat16 hh = __float2bfloat16(hnew);
            __nv_bfloat16 hl = __float2bfloat16(hnew - __bfloat162float(hh));
            g_h_hi[n * HD + j] = hh;
            g_h_lo[n * HD + j] = hl;
            size_t eo = (size_t)(n * LS + t) * HD + j;
            g_eo_hi[eo] = hh;
            g_eo_lo[eo] = hl;
        }
        bt += 16; gsync(g_barc, bt);
    }
}

// ---------------- decoder persistent kernel --------------------------------
__global__ __launch_bounds__(256) void dec_kernel(
    const int* __restrict__ target, const float* __restrict__ Whh,
    const float* __restrict__ bhh)
{
    __shared__ __nv_bfloat16 sWh[48 * SW_STR];
    __shared__ __nv_bfloat16 sWl[48 * SW_STR];
    __shared__ __nv_bfloat16 sHh[128 * SH_STR];
    __shared__ __nv_bfloat16 sHl[128 * SH_STR];

    const int tid = threadIdx.x;
    const int bid = blockIdx.x;
    const int wid = tid >> 5;
    const int lane = tid & 31;
    const int gid = lane >> 2;
    const int q2 = (lane & 3) * 2;
    const int mw = wid & 3;
    const int nw = wid >> 2;
    const int ksl = bid & 3;
    const int jb = bid >> 2;
    const int j0 = jb * 16, kb = ksl * 128;

    RNN_LOAD_W(Whh)
    __syncthreads();

    unsigned bt = 0;
    for (int t = 0; t < TT; ++t) {
        RNN_GEMM_BODY()
        bt += 16; gsync(g_barc + 512, bt);

        int Gt = bid * 256 + tid;
#pragma unroll
        for (int e = 0; e < 2; ++e) {
            int idx = Gt + e * 32768;
            int n = idx >> 9, j = idx & 511;
            int tok = (t == 0) ? 0 : target[n * TT + t - 1];
            const float* ep = g_embp + tok * G3;
            float gir = ep[j], giz = ep[HD + j], gin = ep[2 * HD + j];
            float ghr = bhh[j], ghz = bhh[HD + j], ghn = bhh[2 * HD + j];
#pragma unroll
            for (int q = 0; q < 4; ++q) {
                const float* p = g_ghp + (size_t)(q * NB + n) * G3 + j;
                ghr += __ldcg(p);
                ghz += __ldcg(p + HD);
                ghn += __ldcg(p + 2 * HD);
            }
            float r = sigf(gir + ghr);
            float z = sigf(giz + ghz);
            float nn = tanhf(gin + r * ghn);
            float hold = __bfloat162float(g_h_hi[n * HD + j]) +
                         __bfloat162float(g_h_lo[n * HD + j]);
            float hnew = (1.f - z) * nn + z * hold;
            __nv_bfloat16 hh = __float2bfloat16(hnew);
            __nv_bfloat16 hl = __float2bfloat16(hnew - __bfloat162float(hh));
            g_h_hi[n * HD + j] = hh;
            g_h_lo[n * HD + j] = hl;
            size_t qo = (size_t)(n * TT + t) * HD + j;
            g_q_hi[qo] = hh;
            g_q_lo[qo] = hl;
        }
        bt += 16; gsync(g_barc + 512, bt);
    }
}

// ---------------- dec_hN copy (reconstruct fp32 from hi/lo) -----------------
__global__ void copyh_kernel(float* __restrict__ dst) {
    int i = blockIdx.x * 256 + threadIdx.x;
    dst[i] = __bfloat162float(g_h_hi[i]) + __bfloat162float(g_h_lo[i]);
}

// ---------------- scores via HMMA -------------------------------------------
__global__ __launch_bounds__(256) void scores_kernel(float* __restrict__ outw)
{
    __shared__ __nv_bfloat16 sAh[128 * SH_STR];
    __shared__ __nv_bfloat16 sAl[128 * SH_STR];
    __shared__ __nv_bfloat16 sBh[64 * SH_STR];
    __shared__ __nv_bfloat16 sBl[64 * SH_STR];

    const int tid = threadIdx.x;
    const int bid = blockIdx.x;
    const int n = bid >> 3;
    const int l0 = (bid & 7) * 64;
    const int wid = tid >> 5;
    const int lane = tid & 31;
    const int gid = lane >> 2;
    const int q2 = (lane & 3) * 2;
    const int mw = wid & 3;
    const int nw = wid >> 2;

    const __nv_bfloat16* Ah = g_q_hi + (size_t)n * TT * HD;
    const __nv_bfloat16* Al = g_q_lo + (size_t)n * TT * HD;
    const __nv_bfloat16* Bh = g_eo_hi + (size_t)(n * LS + l0) * HD;
    const __nv_bfloat16* Bl = g_eo_lo + (size_t)(n * LS + l0) * HD;

    float acc[2][4][4];
#pragma unroll
    for (int mt = 0; mt < 2; ++mt)
#pragma unroll
        for (int nt = 0; nt < 4; ++nt)
#pragma unroll
            for (int u = 0; u < 4; ++u) acc[mt][nt][u] = 0.f;

    for (int c = 0; c < 16; ++c) {
        int k0 = c * 32;
        stage_h(sAh, Ah, k0, tid);
        stage_h(sAl, Al, k0, tid);
        {
            int r = tid >> 2, q8 = (tid & 3) * 8;
            uint4 vh = __ldcg((const uint4*)(Bh + (size_t)r * HD + k0 + q8));
            uint4 vl = __ldcg((const uint4*)(Bl + (size_t)r * HD + k0 + q8));
            *(uint4*)((char*)sBh + r * (SH_STR * 2) + q8 * 2) = vh;
            *(uint4*)((char*)sBl + r * (SH_STR * 2) + q8 * 2) = vl;
        }
        __syncthreads();
#pragma unroll
        for (int kk = 0; kk < 2; ++kk) {
            int kl = kk * 16 + q2;
            uint32_t ah[2][4], al[2][4];
#pragma unroll
            for (int mt = 0; mt < 2; ++mt) {
                int r0 = mw * 32 + mt * 16 + gid;
                ah[mt][0] = *(const uint32_t*)&sAh[r0 * SH_STR + kl];
                ah[mt][1] = *(const uint32_t*)&sAh[(r0 + 8) * SH_STR + kl];
                ah[mt][2] = *(const uint32_t*)&sAh[r0 * SH_STR + kl + 8];
                ah[mt][3] = *(const uint32_t*)&sAh[(r0 + 8) * SH_STR + kl + 8];
                al[mt][0] = *(const uint32_t*)&sAl[r0 * SH_STR + kl];
                al[mt][1] = *(const uint32_t*)&sAl[(r0 + 8) * SH_STR + kl];
                al[mt][2] = *(const uint32_t*)&sAl[r0 * SH_STR + kl + 8];
                al[mt][3] = *(const uint32_t*)&sAl[(r0 + 8) * SH_STR + kl + 8];
            }
#pragma unroll
            for (int nt = 0; nt < 4; ++nt) {
                int lr = nw * 32 + nt * 8 + gid;
                uint32_t bh0 = *(const uint32_t*)&sBh[lr * SH_STR + kl];
                uint32_t bh1 = *(const uint32_t*)&sBh[lr * SH_STR + kl + 8];
                uint32_t bl0 = *(const uint32_t*)&sBl[lr * SH_STR + kl];
                uint32_t bl1 = *(const uint32_t*)&sBl[lr * SH_STR + kl + 8];
#pragma unroll
                for (int mt = 0; mt < 2; ++mt) {
                    mma16816(acc[mt][nt], ah[mt][0], ah[mt][1], ah[mt][2],
                             ah[mt][3], bh0, bh1);
                    mma16816(acc[mt][nt], ah[mt][0], ah[mt][1], ah[mt][2],
                             ah[mt][3], bl0, bl1);
                    mma16816(acc[mt][nt], al[mt][0], al[mt][1], al[mt][2],
                             al[mt][3], bh0, bh1);
                }
            }
        }
        __syncthreads();
    }
#pragma unroll
    for (int mt = 0; mt < 2; ++mt)
#pragma unroll
        for (int nt = 0; nt < 4; ++nt) {
            int i = mw * 32 + mt * 16 + gid;
            int l = l0 + nw * 32 + nt * 8 + q2;
            float* op = outw + (size_t)(n * TT + i) * LS + l;
            *(float2*)op = make_float2(acc[mt][nt][0], acc[mt][nt][1]);
            *(float2*)(op + (size_t)8 * LS) =
                make_float2(acc[mt][nt][2], acc[mt][nt][3]);
        }
}

// ---------------- softmax (in-place) + hi/lo emission -----------------------
__global__ void softmax_kernel(float* __restrict__ w)
{
    int row = blockIdx.x * 8 + (threadIdx.x >> 5);
    int lane = threadIdx.x & 31;
    float* p = w + (size_t)row * LS;
    __nv_bfloat16* ph = g_w_hi + (size_t)row * LS;
    __nv_bfloat16* pl = g_w_lo + (size_t)row * LS;
    float v[16];
    float m = -1e30f;
#pragma unroll
    for (int u = 0; u < 16; ++u) { v[u] = p[lane + u * 32]; m = fmaxf(m, v[u]); }
#pragma unroll
    for (int o = 16; o; o >>= 1) m = fmaxf(m, __shfl_xor_sync(0xffffffffu, m, o));
    float s = 0.f;
#pragma unroll
    for (int u = 0; u < 16; ++u) { v[u] = expf(v[u] - m); s += v[u]; }
#pragma unroll
    for (int o = 16; o; o >>= 1) s += __shfl_xor_sync(0xffffffffu, s, o);
    float inv = 1.f / s;
#pragma unroll
    for (int u = 0; u < 16; ++u) {
        float val = v[u] * inv;
        p[lane + u * 32] = val;
        __nv_bfloat16 hh = __float2bfloat16(val);
        ph[lane + u * 32] = hh;
        pl[lane + u * 32] = __float2bfloat16(val - __bfloat162float(hh));
    }
}

// ---------------- ctx via HMMA: C[n][i][h] = sum_l w·E ----------------------
__global__ __launch_bounds__(256) void ctx_kernel(const float* __restrict__ wdummy)
{
    __shared__ __nv_bfloat16 sAh[128 * SH_STR];
    __shared__ __nv_bfloat16 sAl[128 * SH_STR];
    __shared__ __nv_bfloat16 sBh[64 * SH_STR];
    __shared__ __nv_bfloat16 sBl[64 * SH_STR];

    const int tid = threadIdx.x;
    const int bid = blockIdx.x;
    const int n = bid >> 3;
    const int h0 = (bid & 7) * 64;
    const int wid = tid >> 5;
    const int lane = tid & 31;
    const int gid = lane >> 2;
    const int q2 = (lane & 3) * 2;
    const int mw = wid & 3;
    const int nw = wid >> 2;

    const __nv_bfloat16* Ah = g_w_hi + (size_t)n * TT * LS;
    const __nv_bfloat16* Al = g_w_lo + (size_t)n * TT * LS;

    float acc[2][4][4];
#pragma unroll
    for (int mt = 0; mt < 2; ++mt)
#pragma unroll
        for (int nt = 0; nt < 4; ++nt)
#pragma unroll
            for (int u = 0; u < 4; ++u) acc[mt][nt][u] = 0.f;

    for (int c = 0; c < 16; ++c) {
        int k0 = c * 32;                 // l chunk
        stage_h(sAh, Ah, k0, tid);
        stage_h(sAl, Al, k0, tid);
        {
            int r = tid >> 3, hc = (tid & 7) * 8;
            size_t base = (size_t)(n * LS + k0 + r) * HD + h0 + hc;
            uint4 vh = __ldcg((const uint4*)(g_eo_hi + base));
            uint4 vl = __ldcg((const uint4*)(g_eo_lo + base));
            const __nv_bfloat16* eh = (const __nv_bfloat16*)&vh;
            const __nv_bfloat16* el = (const __nv_bfloat16*)&vl;
#pragma unroll
            for (int u = 0; u < 8; ++u) {
                sBh[(hc + u) * SH_STR + r] = eh[u];
                sBl[(hc + u) * SH_STR + r] = el[u];
            }
        }
        __syncthreads();
#pragma unroll
        for (int kk = 0; kk < 2; ++kk) {
            int kl = kk * 16 + q2;
            uint32_t ah[2][4], al[2][4];
#pragma unroll
            for (int mt = 0; mt < 2; ++mt) {
                int r0 = mw * 32 + mt * 16 + gid;
                ah[mt][0] = *(const uint32_t*)&sAh[r0 * SH_STR + kl];
                ah[mt][1] = *(const uint32_t*)&sAh[(r0 + 8) * SH_STR + kl];
                ah[mt][2] = *(const uint32_t*)&sAh[r0 * SH_STR + kl + 8];
                ah[mt][3] = *(const uint32_t*)&sAh[(r0 + 8) * SH_STR + kl + 8];
                al[mt][0] = *(const uint32_t*)&sAl[r0 * SH_STR + kl];
                al[mt][1] = *(const uint32_t*)&sAl[(r0 + 8) * SH_STR + kl];
                al[mt][2] = *(const uint32_t*)&sAl[r0 * SH_STR + kl + 8];
                al[mt][3] = *(const uint32_t*)&sAl[(r0 + 8) * SH_STR + kl + 8];
            }
#pragma unroll
            for (int nt = 0; nt < 4; ++nt) {
                int hr = nw * 32 + nt * 8 + gid;
                uint32_t bh0 = *(const uint32_t*)&sBh[hr * SH_STR + kl];
                uint32_t bh1 = *(const uint32_t*)&sBh[hr * SH_STR + kl + 8];
                uint32_t bl0 = *(const uint32_t*)&sBl[hr * SH_STR + kl];
                uint32_t bl1 = *(const uint32_t*)&sBl[hr * SH_STR + kl + 8];
#pragma unroll
                for (int mt = 0; mt < 2; ++mt) {
                    mma16816(acc[mt][nt], ah[mt][0], ah[mt][1], ah[mt][2],
                             ah[mt][3], bh0, bh1);
                    mma16816(acc[mt][nt], ah[mt][0], ah[mt][1], ah[mt][2],
                             ah[mt][3], bl0, bl1);
                    mma16816(acc[mt][nt], al[mt][0], al[mt][1], al[mt][2],
                             al[mt][3], bh0, bh1);
                }
            }
        }
        __syncthreads();
    }
#pragma unroll
    for (int mt = 0; mt < 2; ++mt)
#pragma unroll
        for (int nt = 0; nt < 4; ++nt) {
            int i = mw * 32 + mt * 16 + gid;
            int h = h0 + nw * 32 + nt * 8 + q2;
#pragma unroll
            for (int rr = 0; rr < 2; ++rr) {
                float v0 = acc[mt][nt][rr * 2 + 0];
                float v1 = acc[mt][nt][rr * 2 + 1];
                size_t o = (size_t)(n * TT + i + rr * 8) * HD + h;
                __nv_bfloat16 h0b = __float2bfloat16(v0);
                __nv_bfloat16 h1b = __float2bfloat16(v1);
                __nv_bfloat162 hv; hv.x = h0b; hv.y = h1b;
                *(__nv_bfloat162*)(g_cx_hi + o) = hv;
                __nv_bfloat162 lv;
                lv.x = __float2bfloat16(v0 - __bfloat162float(h0b));
                lv.y = __float2bfloat16(v1 - __bfloat162float(h1b));
                *(__nv_bfloat162*)(g_cx_lo + o) = lv;
            }
        }
}

// ---------------- ff via HMMA: g_ff = [Q|ctx] @ W^T + b ---------------------
__global__ __launch_bounds__(256) void ff_kernel(
    const float* __restrict__ W, const float* __restrict__ b)
{
    __shared__ __nv_bfloat16 sAh[128 * SH_STR];
    __shared__ __nv_bfloat16 sAl[128 * SH_STR];
    __shared__ __nv_bfloat16 sBh[64 * SH_STR];
    __shared__ __nv_bfloat16 sBl[64 * SH_STR];

    const int tid = threadIdx.x;
    const int bid = blockIdx.x;
    const int m0 = (bid >> 3) * 128;
    const int o0 = (bid & 7) * 64;
    const int wid = tid >> 5;
    const int lane = tid & 31;
    const int gid = lane >> 2;
    const int q2 = (lane & 3) * 2;
    const int mw = wid & 3;
    const int nw = wid >> 2;

    float acc[2][4][4];
#pragma unroll
    for (int mt = 0; mt < 2; ++mt)
#pragma unroll
        for (int nt = 0; nt < 4; ++nt)
#pragma unroll
            for (int u = 0; u < 4; ++u) acc[mt][nt][u] = 0.f;

    for (int c = 0; c < 32; ++c) {
        int k0 = c * 32;
        const __nv_bfloat16* Ah =
            (k0 < HD) ? (g_q_hi + (size_t)m0 * HD) : (g_cx_hi + (size_t)m0 * HD);
        const __nv_bfloat16* Al =
            (k0 < HD) ? (g_q_lo + (size_t)m0 * HD) : (g_cx_lo + (size_t)m0 * HD);
        int koff = (k0 < HD) ? k0 : k0 - HD;
        stage_h(sAh, Ah, koff, tid);
        stage_h(sAl, Al, koff, tid);
        {
            int r = tid >> 2, q8 = (tid & 3) * 8;
            const float4* wp = (const float4*)(W + (size_t)(o0 + r) * (2 * HD) + k0 + q8);
            float4 w0 = __ldcg(wp);
            float4 w1 = __ldcg(wp + 1);
            float wv[8] = {w0.x, w0.y, w0.z, w0.w, w1.x, w1.y, w1.z, w1.w};
#pragma unroll
            for (int u = 0; u < 8; u += 2) {
                __nv_bfloat16 h0b = __float2bfloat16(wv[u]);
                __nv_bfloat16 h1b = __float2bfloat16(wv[u + 1]);
                __nv_bfloat162 hv; hv.x = h0b; hv.y = h1b;
                *(__nv_bfloat162*)&sBh[r * SH_STR + q8 + u] = hv;
                __nv_bfloat162 lv;
                lv.x = __float2bfloat16(wv[u] - __bfloat162float(h0b));
                lv.y = __float2bfloat16(wv[u + 1] - __bfloat162float(h1b));
                *(__nv_bfloat162*)&sBl[r * SH_STR + q8 + u] = lv;
            }
        }
        __syncthreads();
#pragma unroll
        for (int kk = 0; kk < 2; ++kk) {
            int kl = kk * 16 + q2;
            uint32_t ah[2][4], al[2][4];
#pragma unroll
            for (int mt = 0; mt < 2; ++mt) {
                int r0 = mw * 32 + mt * 16 + gid;
                ah[mt][0] = *(const uint32_t*)&sAh[r0 * SH_STR + kl];
                ah[mt][1] = *(const uint32_t*)&sAh[(r0 + 8) * SH_STR + kl];
                ah[mt][2] = *(const uint32_t*)&sAh[r0 * SH_STR + kl + 8];
                ah[mt][3] = *(const uint32_t*)&sAh[(r0 + 8) * SH_STR + kl + 8];
                al[mt][0] = *(const uint32_t*)&sAl[r0 * SH_STR + kl];
                al[mt][1] = *(const uint32_t*)&sAl[(r0 + 8) * SH_STR + kl];
                al[mt][2] = *(const uint32_t*)&sAl[r0 * SH_STR + kl + 8];
                al[mt][3] = *(const uint32_t*)&sAl[(r0 + 8) * SH_STR + kl + 8];
            }
#pragma unroll
            for (int nt = 0; nt < 4; ++nt) {
                int orow = nw * 32 + nt * 8 + gid;
                uint32_t bh0 = *(const uint32_t*)&sBh[orow * SH_STR + kl];
                uint32_t bh1 = *(const uint32_t*)&sBh[orow * SH_STR + kl + 8];
                uint32_t bl0 = *(const uint32_t*)&sBl[orow * SH_STR + kl];
                uint32_t bl1 = *(const uint32_t*)&sBl[orow * SH_STR + kl + 8];
#pragma unroll
                for (int mt = 0; mt < 2; ++mt) {
                    mma16816(acc[mt][nt], ah[mt][0], ah[mt][1], ah[mt][2],
                             ah[mt][3], bh0, bh1);
                    mma16816(acc[mt][nt], ah[mt][0], ah[mt][1], ah[mt][2],
                             ah[mt][3], bl0, bl1);
                    mma16816(acc[mt][nt], al[mt][0], al[mt][1], al[mt][2],
                             al[mt][3], bh0, bh1);
                }
            }
        }
        __syncthreads();
    }
#pragma unroll
    for (int mt = 0; mt < 2; ++mt)
#pragma unroll
        for (int nt = 0; nt < 4; ++nt) {
            int i = mw * 32 + mt * 16 + gid;
            int o = o0 + nw * 32 + nt * 8 + q2;
            float b0 = b[o], b1 = b[o + 1];
            float* op = g_ff + (size_t)(m0 + i) * HD + o;
            *(float2*)op = make_float2(acc[mt][nt][0] + b0, acc[mt][nt][1] + b1);
            *(float2*)(op + (size_t)8 * HD) =
                make_float2(acc[mt][nt][2] + b0, acc[mt][nt][3] + b1);
        }
}

// ---------------- fc ---------------------------------------------------------
__global__ __launch_bounds__(256) void fc_kernel(
    const float* __restrict__ W, const float* __restrict__ b,
    float* __restrict__ vout)
{
    __shared__ float sa[128][36], swt[64][36];
    int m0 = blockIdx.x * 128;
    int tid = threadIdx.x, tx = tid & 15, ty = tid >> 4;
    float acc[8][4];
#pragma unroll
    for (int i = 0; i < 8; i++)
#pragma unroll
        for (int s = 0; s < 4; s++) acc[i][s] = 0.f;

    for (int st = 0; st < 16; ++st) {
        int k0 = st * 32;
        for (int v = tid; v < 1024; v += 256) {
            int r = v >> 3, c = (v & 7) * 4;
            *(float4*)&sa[r][c] = *(const float4*)(g_ff + (size_t)(m0 + r) * HD + k0 + c);
        }
        for (int v = tid; v < 512; v += 256) {
            int r = v >> 3, c = (v & 7) * 4;
            *(float4*)&swt[r][c] = *(const float4*)(W + (size_t)r * HD + k0 + c);
        }
        __syncthreads();
#pragma unroll
        for (int k = 0; k < 32; ++k) {
            float av[8], wv[4];
#pragma unroll
            for (int i = 0; i < 8; i++) av[i] = sa[ty * 8 + i][k];
#pragma unroll
            for (int s = 0; s < 4; s++) wv[s] = swt[tx * 4 + s][k];
#pragma unroll
            for (int i = 0; i < 8; i++)
#pragma unroll
                for (int s = 0; s < 4; s++)
                    acc[i][s] = fmaf(av[i], wv[s], acc[i][s]);
        }
        __syncthreads();
    }
#pragma unroll
    for (int i = 0; i < 8; i++)
#pragma unroll
        for (int s = 0; s < 4; s++)
            vout[(size_t)(m0 + ty * 8 + i) * SS + tx * 4 + s] = acc[i][s] + b[tx * 4 + s];
}

// ---------------- launch ----------------------------------------------------
extern "C" void kernel_launch(void* const* d_in, const int* in_sizes, int n_in,
                              void* d_out, int out_size)
{
    const float* x      = (const float*)d_in[0];
    const int*   target = (const int*)  d_in[1];
    const float* eWih   = (const float*)d_in[2];
    const float* eWhh   = (const float*)d_in[3];
    const float* ebih   = (const float*)d_in[4];
    const float* ebhh   = (const float*)d_in[5];
    const float* dWih   = (const float*)d_in[6];
    const float* dWhh   = (const float*)d_in[7];
    const float* dbih   = (const float*)d_in[8];
    const float* dbhh   = (const float*)d_in[9];
    const float* emb    = (const float*)d_in[10];
    const float* aW     = (const float*)d_in[11];
    const float* ab     = (const float*)d_in[12];
    const float* fW     = (const float*)d_in[13];
    const float* fb     = (const float*)d_in[14];

    float* out   = (float*)d_out;
    float* v_out = out;                       // (128,128,64)
    float* hN    = out + 1048576;             // (1,128,512)
    float* allw  = out + 1048576 + 65536;     // (128,128,512)

    init_enc_kernel<<<256, 256>>>();
    embproj_kernel<<<64, 256>>>(emb, dWih, dbih);
    enc_kernel<<<128, 256>>>(x, eWih, eWhh, ebih, ebhh);
    dec_kernel<<<128, 256>>>(target, dWhh, dbhh);
    copyh_kernel<<<256, 256>>>(hN);
    scores_kernel<<<1024, 256>>>(allw);
    softmax_kernel<<<2048, 256>>>(allw);
    ctx_kernel<<<1024, 256>>>(allw);
    ff_kernel<<<1024, 256>>>(aW, ab);
    fc_kernel<<<128, 256>>>(fW, fb, v_out);
}